// round 10
// baseline (speedup 1.0000x reference)
#include <cuda_runtime.h>
#include <math.h>

// Problem constants
#define Bv 4
#define Nv 8192
#define Sv 12
#define Lv 5
#define Ev 131072
#define CAP 128
#define BN (Bv*Nv)        // 32768 sequences
#define FSZ (Bv*Nv*Sv)    // floats per feature map

// ---------------- scratch ----------------
__device__ float g_xpA[FSZ], g_xpB[FSZ];
__device__ float g_c1A[FSZ], g_c1B[FSZ];
__device__ float g_c2A[FSZ], g_c2B[FSZ];
__device__ float g_c4A[FSZ], g_c4B[FSZ];
__device__ float g_c5A[FSZ], g_c5B[FSZ];

__device__ int g_fill [2][Nv];
__device__ int g_ci   [2][Nv*CAP];
__device__ int g_ucnt [2][Nv];
__device__ int g_uci  [2][Nv*CAP];
__device__ int g_mult [2][Nv*CAP];
__device__ int g_rfill[2][Nv];
__device__ int g_reid [2][Nv*CAP];

__device__ float g_p[2][Nv];          // per paired-stage slot
__device__ float g_q[2][Nv];
__device__ float g_w[2][Nv*CAP];
__device__ float g_esum[4][Bv*Sv];    // per-stage-slot rank-1 correction

__device__ __forceinline__ const float* bufA(int id) {
    switch (id) { case 0: return g_xpA; case 1: return g_c1A; case 2: return g_c2A;
                  case 3: return g_c4A; default: return g_c5A; }
}
__device__ __forceinline__ float* bufAw(int id) {
    switch (id) { case 0: return g_xpA; case 1: return g_c1A; case 2: return g_c2A;
                  case 3: return g_c4A; default: return g_c5A; }
}
__device__ __forceinline__ float* bufBw(int id) {
    switch (id) { case 0: return g_xpB; case 1: return g_c1B; case 2: return g_c2B;
                  case 3: return g_c4B; default: return g_c5B; }
}

// single-MUFU activations (sm_75+ tanh.approx)
__device__ __forceinline__ float tanh_ap(float x) {
    float y;
    asm("tanh.approx.f32 %0, %1;" : "=f"(y) : "f"(x));
    return y;
}
__device__ __forceinline__ float sigmf(float x) {
    return 0.5f * tanh_ap(0.5f * x) + 0.5f;
}

// ---------------- fused transpose + bucket (fill zeroed by memset node) ----
#define TRB ((FSZ + 255) / 256)      // transpose blocks
#define BKB ((2 * Ev + 255) / 256)   // bucket blocks
__global__ void k_initbucket(const float* __restrict__ x,
                             const int* __restrict__ e1,
                             const int* __restrict__ e2) {
    if (blockIdx.x < TRB) {
        int idx = blockIdx.x * 256 + threadIdx.x;
        if (idx >= FSZ) return;
        int n = idx % Nv;
        int r = idx / Nv;
        int s = r % Sv;
        int b = r / Sv;
        float v = x[idx];
        g_xpA[(b * Nv + n) * Sv + s] = v;
        g_xpB[s * BN + b * Nv + n]   = v;
    } else {
        int k = (blockIdx.x - TRB) * 256 + threadIdx.x;
        if (k >= 2 * Ev) return;
        int lid = k >= Ev;
        int kk = k - lid * Ev;
        const int* ed = lid ? e2 : e1;
        int i = ed[kk];
        int j = ed[Ev + kk];
        int pos = atomicAdd(&g_fill[lid][j], 1);
        if (pos < CAP) g_ci[lid][j * CAP + pos] = i;
    }
}

// warp-per-column dedup + fused row-CSR build + fused pq for pair A
#define DWPB 8
#define NDBLK ((2 * Nv) / DWPB)
__global__ void k_dedup2(const float* __restrict__ g1W, const float* __restrict__ g1a,
                         const float* __restrict__ g2W, const float* __restrict__ g2a) {
    if (blockIdx.x >= NDBLK) {
        // ---- pq for pair A: slot0 = g1 on xp, slot1 = g2 on xp ----
        __shared__ float wa[2][Sv], wb[2][Sv];
        int t = threadIdx.x;
        if (t < Sv) {
            float s1 = 0.f, s2 = 0.f;
            #pragma unroll
            for (int u = 0; u < Sv; u++) {
                float w = g1W[t * Sv + u];
                s1 += w * g1a[u];
                s2 += w * g1a[Sv + u];
            }
            wa[0][t] = s1; wb[0][t] = s2;
        } else if (t >= 32 && t < 32 + Sv) {
            int tt = t - 32;
            float s1 = 0.f, s2 = 0.f;
            #pragma unroll
            for (int u = 0; u < Sv; u++) {
                float w = g2W[tt * Sv + u];
                s1 += w * g2a[u];
                s2 += w * g2a[Sv + u];
            }
            wa[1][tt] = s1; wb[1][tt] = s2;
        }
        __syncthreads();
        int i = (blockIdx.x - NDBLK) * blockDim.x + threadIdx.x;
        if (i >= Nv) return;
        float pA = 0.f, qA = 0.f, pB = 0.f, qB = 0.f;
        #pragma unroll
        for (int s = 0; s < Sv; s++) {
            float v = g_xpA[i * Sv + s];
            pA += v * wa[0][s]; qA += v * wb[0][s];
            pB += v * wa[1][s]; qB += v * wb[1][s];
        }
        g_p[0][i] = pA; g_q[0][i] = qA;
        g_p[1][i] = pB; g_q[1][i] = qB;
        return;
    }

    __shared__ int s_ci[DWPB][CAP];
    int warp = threadIdx.x >> 5;
    int lane = threadIdx.x & 31;
    int jj = blockIdx.x * DWPB + warp;
    int lid = jj >= Nv;
    int j = jj - lid * Nv;
    int k = min(g_fill[lid][j], CAP);
    const int* ci = g_ci[lid] + j * CAP;
    for (int t = lane; t < k; t += 32) s_ci[warp][t] = ci[t];
    __syncwarp();
    int* uci = g_uci[lid] + j * CAP;
    int* mlt = g_mult[lid] + j * CAP;
    int base = 0;
    for (int c = 0; c < k; c += 32) {
        int idx = c + lane;
        bool valid = idx < k;
        int i = valid ? s_ci[warp][idx] : -1;
        bool leader = valid;
        int mult = 0;
        if (valid) {
            for (int t = 0; t < idx; t++)
                if (s_ci[warp][t] == i) { leader = false; break; }
            if (leader)
                for (int t = idx; t < k; t++)
                    if (s_ci[warp][t] == i) mult++;
        }
        unsigned bal = __ballot_sync(0xFFFFFFFF, leader);
        if (leader) {
            int pos = base + __popc(bal & ((1u << lane) - 1));
            uci[pos] = i; mlt[pos] = mult;
            int rp = atomicAdd(&g_rfill[lid][i], 1);
            if (rp < CAP) g_reid[lid][i * CAP + rp] = j * CAP + pos;
        }
        base += __popc(bal);
    }
    if (lane == 0) g_ucnt[lid][j] = base;
}

// warp-per-column softmax; slot A uses list lidA, slot B list lidB
__global__ void k_colw2(int lidA, int lidB, int xidA, int xidB, int esumBase,
                        const float* __restrict__ lwA, const float* __restrict__ lbA,
                        const float* __restrict__ lwB, const float* __restrict__ lbB) {
    int warp = threadIdx.x >> 5;
    int lane = threadIdx.x & 31;
    int jj = blockIdx.x * (blockDim.x >> 5) + warp;
    if (jj >= 2 * Nv) return;
    int sid = jj >= Nv;
    int j = jj - sid * Nv;
    int lid = sid ? lidB : lidA;
    int u = g_ucnt[lid][j];
    if (u == 0) {
        const float* X = bufA(sid ? xidB : xidA);
        for (int t = lane; t < Bv * Sv; t += 32) {
            int b = t / Sv, s = t - b * Sv;
            atomicAdd(&g_esum[esumBase + sid][t], X[(b * Nv + j) * Sv + s]);
        }
        return;
    }
    const int* uci = g_uci[lid] + j * CAP;
    const int* mlt = g_mult[lid] + j * CAP;
    float* wv = g_w[sid] + j * CAP;
    float qj = g_q[sid][j];
    float lwv = sid ? lwB[0] : lwA[0];
    float lbv = sid ? lbB[0] : lbA[0];
    float vals[4];
    int cnt = 0;
    float m = -1e30f;
    for (int t = lane; t < u; t += 32) {
        float e = g_p[sid][uci[t]] + qj;
        e = (e > 0.f) ? e : 0.2f * e;
        float val = (float)mlt[t] * (e * lwv + lbv);
        vals[cnt++] = val;
        m = fmaxf(m, val);
    }
    #pragma unroll
    for (int o = 16; o; o >>= 1) m = fmaxf(m, __shfl_xor_sync(0xFFFFFFFF, m, o));
    float den = 0.f;
    for (int c = 0; c < cnt; c++) {
        vals[c] = __expf(vals[c] - m);
        den += vals[c];
    }
    #pragma unroll
    for (int o = 16; o; o >>= 1) den += __shfl_xor_sync(0xFFFFFFFF, den, o);
    float inv = 1.0f / den;
    cnt = 0;
    for (int t = lane; t < u; t += 32) wv[t] = vals[cnt++] * inv;
}

// gather SpMM + fused GCN; 8 threads per (slot,b,i), shuffle reduction.
#define GSUB 8
__global__ void k_gather2(int lidA, int lidB, int xidA, int xidB,
                          int outA, int outB, int esumBase, int doPQ,
                          const float* __restrict__ gcnW,
                          const float* __restrict__ gcnb,
                          const float* __restrict__ g1W, const float* __restrict__ g1a,
                          const float* __restrict__ g2W, const float* __restrict__ g2a) {
    __shared__ float sW[Sv * Sv], sb[Sv];
    __shared__ float wa[2][Sv], wb[2][Sv];
    int tx = threadIdx.x;
    if (tx < Sv * Sv) sW[tx] = gcnW[tx];
    if (tx < Sv) sb[tx] = gcnb[tx];
    if (doPQ) {
        if (tx < Sv) {
            float s1 = 0.f, s2 = 0.f;
            #pragma unroll
            for (int u = 0; u < Sv; u++) {
                float w = g1W[tx * Sv + u];
                s1 += w * g1a[u];
                s2 += w * g1a[Sv + u];
            }
            wa[0][tx] = s1; wb[0][tx] = s2;
        } else if (tx >= 32 && tx < 32 + Sv) {
            int tt = tx - 32;
            float s1 = 0.f, s2 = 0.f;
            #pragma unroll
            for (int u = 0; u < Sv; u++) {
                float w = g2W[tt * Sv + u];
                s1 += w * g2a[u];
                s2 += w * g2a[Sv + u];
            }
            wa[1][tt] = s1; wb[1][tt] = s2;
        }
    }
    __syncthreads();

    int gtid = blockIdx.x * blockDim.x + threadIdx.x;
    int gid = gtid / GSUB;      // (slot,b,i) id
    int sub = gtid % GSUB;
    if (gid >= 2 * BN) return;
    int sid = gid >= BN;
    int rem = gid - sid * BN;
    int i = rem & (Nv - 1);
    int b = rem >> 13;
    int lid = sid ? lidB : lidA;

    const float* X = bufA(sid ? xidB : xidA);
    const int* reid = g_reid[lid] + i * CAP;
    const float* wv = g_w[sid];
    int deg = min(g_rfill[lid][i], CAP);

    float z[Sv];
    #pragma unroll
    for (int s = 0; s < Sv; s++) z[s] = 0.f;

    for (int t = sub; t < deg; t += GSUB) {
        int eid = reid[t];
        float w = wv[eid];
        int j = eid >> 7;   // CAP = 128
        const float4* xr = (const float4*)(X + (b * Nv + j) * Sv);
        float4 v0 = xr[0], v1 = xr[1], v2 = xr[2];
        z[0] += w * v0.x; z[1] += w * v0.y; z[2]  += w * v0.z; z[3]  += w * v0.w;
        z[4] += w * v1.x; z[5] += w * v1.y; z[6]  += w * v1.z; z[7]  += w * v1.w;
        z[8] += w * v2.x; z[9] += w * v2.y; z[10] += w * v2.z; z[11] += w * v2.w;
    }
    #pragma unroll
    for (int o = 1; o < GSUB; o <<= 1) {
        #pragma unroll
        for (int s = 0; s < Sv; s++)
            z[s] += __shfl_xor_sync(0xFFFFFFFF, z[s], o);
    }
    if (sub != 0) return;

    #pragma unroll
    for (int s = 0; s < Sv; s++)
        z[s] += g_esum[esumBase + sid][b * Sv + s] * (1.0f / (float)Nv);

    float* OA = bufAw(sid ? outB : outA);
    float* OB = bufBw(sid ? outB : outA);
    int tid = b * Nv + i;
    float pN = 0.f, qN = 0.f;
    #pragma unroll
    for (int s = 0; s < Sv; s++) {
        float y = sb[s];
        #pragma unroll
        for (int t = 0; t < Sv; t++) y += z[t] * sW[s * Sv + t];
        y = (y > 0.f) ? y : 0.01f * y;
        OA[tid * Sv + s] = y;
        OB[s * BN + tid] = y;
        pN += y * wa[sid][s];
        qN += y * wb[sid][s];
    }
    if (doPQ && b == 0) {
        g_p[sid][i] = pN;
        g_q[sid][i] = qN;
    }
}

// ---------------- fused 2-layer LSTM + TPA head ----------------
// 148 blocks x 224 threads: exactly one block per SM, single balanced wave.
#define LSTM_TB 224
#define LSTM_GB 148
__global__ void __launch_bounds__(LSTM_TB)
k_lstm(const float* __restrict__ Wih0, const float* __restrict__ Whh0,
       const float* __restrict__ bih0, const float* __restrict__ bhh0,
       const float* __restrict__ Wih1, const float* __restrict__ Whh1,
       const float* __restrict__ bih1, const float* __restrict__ bhh1,
       const float* __restrict__ fc1W, const float* __restrict__ fc1b,
       const float* __restrict__ fc2W, const float* __restrict__ fc2b,
       const float* __restrict__ fc3W, const float* __restrict__ fc3b,
       float* __restrict__ out, int out_size) {
    __shared__ float sWih0[100], sWhh0[100], sB0[20];
    __shared__ float sWih1[100], sWhh1[100], sB1[20];
    __shared__ float sF1[176], sF1b[16], sF2[80], sF2b[5], sF3[21], sF3b;
    int t = threadIdx.x;
    for (int i = t; i < 100; i += blockDim.x) {
        sWih0[i] = Wih0[i]; sWhh0[i] = Whh0[i];
        sWih1[i] = Wih1[i]; sWhh1[i] = Whh1[i];
    }
    for (int i = t; i < 20; i += blockDim.x) {
        sB0[i] = bih0[i] + bhh0[i];
        sB1[i] = bih1[i] + bhh1[i];
    }
    for (int i = t; i < 176; i += blockDim.x) sF1[i] = fc1W[i];
    for (int i = t; i < 80;  i += blockDim.x) sF2[i] = fc2W[i];
    for (int i = t; i < 21;  i += blockDim.x) sF3[i] = fc3W[i];
    for (int i = t; i < 16;  i += blockDim.x) sF1b[i] = fc1b[i];
    for (int i = t; i < 5;   i += blockDim.x) sF2b[i] = fc2b[i];
    if (t == 0) sF3b = fc3b[0];
    __syncthreads();

    int seq = blockIdx.x * blockDim.x + threadIdx.x;
    if (seq >= BN) return;

    float h0[Lv], c0[Lv], h1[Lv], c1l[Lv];
    #pragma unroll
    for (int l = 0; l < Lv; l++) { h0[l]=0.f; c0[l]=0.f; h1[l]=0.f; c1l[l]=0.f; }

    float Hc[Lv][16];
    #pragma unroll
    for (int l = 0; l < Lv; l++)
        #pragma unroll
        for (int k = 0; k < 16; k++)
            Hc[l][k] = sF1b[k];

    #pragma unroll 1
    for (int tt = 0; tt < Sv; tt++) {
        float xv[Lv];
        xv[0] = g_xpB[tt * BN + seq];
        xv[1] = g_c1B[tt * BN + seq];
        xv[2] = g_c2B[tt * BN + seq];
        xv[3] = g_c4B[tt * BN + seq];
        xv[4] = g_c5B[tt * BN + seq];

        float z[20];
        #pragma unroll
        for (int g = 0; g < 20; g++) {
            float zz = sB0[g];
            #pragma unroll
            for (int l = 0; l < Lv; l++)
                zz += sWih0[g * Lv + l] * xv[l] + sWhh0[g * Lv + l] * h0[l];
            z[g] = zz;
        }
        #pragma unroll
        for (int l = 0; l < Lv; l++) {
            float ig = sigmf(z[l]);
            float fg = sigmf(z[5 + l]);
            float gg = tanh_ap(z[10 + l]);
            float og = sigmf(z[15 + l]);
            c0[l] = fg * c0[l] + ig * gg;
            h0[l] = og * tanh_ap(c0[l]);
        }
        #pragma unroll
        for (int g = 0; g < 20; g++) {
            float zz = sB1[g];
            #pragma unroll
            for (int l = 0; l < Lv; l++)
                zz += sWih1[g * Lv + l] * h0[l] + sWhh1[g * Lv + l] * h1[l];
            z[g] = zz;
        }
        #pragma unroll
        for (int l = 0; l < Lv; l++) {
            float ig = sigmf(z[l]);
            float fg = sigmf(z[5 + l]);
            float gg = tanh_ap(z[10 + l]);
            float og = sigmf(z[15 + l]);
            c1l[l] = fg * c1l[l] + ig * gg;
            h1[l] = og * tanh_ap(c1l[l]);
        }
        if (tt < Sv - 1) {
            #pragma unroll
            for (int l = 0; l < Lv; l++) {
                float hv = h1[l];
                #pragma unroll
                for (int k = 0; k < 16; k++)
                    Hc[l][k] += hv * sF1[k * (Sv - 1) + tt];
            }
        }
    }

    float ht[Lv];
    #pragma unroll
    for (int m = 0; m < Lv; m++) ht[m] = h1[m];

    float av[Lv];
    #pragma unroll
    for (int l = 0; l < Lv; l++) {
        float s = 0.f;
        #pragma unroll
        for (int m = 0; m < Lv; m++) {
            float hn = sF2b[m];
            #pragma unroll
            for (int k = 0; k < 16; k++) hn += Hc[l][k] * sF2[m * 16 + k];
            s += hn * ht[m];
        }
        av[l] = sigmf(s);
    }

    float y = sF3b;
    #pragma unroll
    for (int k = 0; k < 16; k++) {
        float vt = 0.f;
        #pragma unroll
        for (int l = 0; l < Lv; l++) vt += av[l] * Hc[l][k];
        y += vt * sF3[k];
    }
    #pragma unroll
    for (int m = 0; m < Lv; m++) y += ht[m] * sF3[16 + m];

    out[seq] = y;
    if (BN + seq * Lv + (Lv - 1) < out_size) {
        #pragma unroll
        for (int l = 0; l < Lv; l++)
            out[BN + seq * Lv + l] = av[l];
    }
}

// ---------------- launcher ----------------
extern "C" void kernel_launch(void* const* d_in, const int* in_sizes, int n_in,
                              void* d_out, int out_size) {
    const float* x    = (const float*)d_in[0];
    const int*   e1   = (const int*)  d_in[1];
    const int*   e2   = (const int*)  d_in[2];
    const float* g1W  = (const float*)d_in[3];
    const float* g1a  = (const float*)d_in[4];
    const float* g1lw = (const float*)d_in[5];
    const float* g1lb = (const float*)d_in[6];
    const float* g2W  = (const float*)d_in[7];
    const float* g2a  = (const float*)d_in[8];
    const float* g2lw = (const float*)d_in[9];
    const float* g2lb = (const float*)d_in[10];
    const float* gcnW = (const float*)d_in[11];
    const float* gcnb = (const float*)d_in[12];
    const float* Wih0 = (const float*)d_in[13];
    const float* Whh0 = (const float*)d_in[14];
    const float* bih0 = (const float*)d_in[15];
    const float* bhh0 = (const float*)d_in[16];
    const float* Wih1 = (const float*)d_in[17];
    const float* Whh1 = (const float*)d_in[18];
    const float* bih1 = (const float*)d_in[19];
    const float* bhh1 = (const float*)d_in[20];
    const float* fc1W = (const float*)d_in[21];
    const float* fc1b = (const float*)d_in[22];
    const float* fc2W = (const float*)d_in[23];
    const float* fc2b = (const float*)d_in[24];
    const float* fc3W = (const float*)d_in[25];
    const float* fc3b = (const float*)d_in[26];

    const int TB = 256;

    // zero counters via memset nodes (not kernel launches)
    void *pFill, *pRfill, *pEsum;
    cudaGetSymbolAddress(&pFill,  g_fill);
    cudaGetSymbolAddress(&pRfill, g_rfill);
    cudaGetSymbolAddress(&pEsum,  g_esum);
    cudaMemsetAsync(pFill,  0, sizeof(int) * 2 * Nv);
    cudaMemsetAsync(pRfill, 0, sizeof(int) * 2 * Nv);
    cudaMemsetAsync(pEsum,  0, sizeof(float) * 4 * Bv * Sv);

    // launch 0: fused transpose + bucket
    k_initbucket<<<TRB + BKB, 256>>>(x, e1, e2);
    // launch 1: dedup + fused rowbuild + fused pq for pair A
    k_dedup2<<<NDBLK + (Nv + TB - 1) / TB, TB>>>(g1W, g1a, g2W, g2a);

    // pair A: stage0 (list0, xp -> c1) + stage2 (list1, xp -> c4)
    k_colw2<<<(2 * Nv) / 8, 256>>>(0, 1, 0, 0, 0, g1lw, g1lb, g2lw, g2lb);          // 2
    k_gather2<<<(2 * BN * GSUB) / TB, TB>>>(0, 1, 0, 0, 1, 3, 0, 1,                 // 3
                                            gcnW, gcnb, g1W, g1a, g2W, g2a);

    // pair B: stage1 (list0, c1 -> c2) + stage3 (list1, c4 -> c5)
    k_colw2<<<(2 * Nv) / 8, 256>>>(0, 1, 1, 3, 2, g1lw, g1lb, g2lw, g2lb);          // 4
    k_gather2<<<(2 * BN * GSUB) / TB, TB>>>(0, 1, 1, 3, 2, 5, 2, 0,                 // 5 <- ncu sample
                                            gcnW, gcnb, g1W, g1a, g2W, g2a);

    k_lstm<<<LSTM_GB, LSTM_TB>>>(Wih0, Whh0, bih0, bhh0,                            // 6
                                 Wih1, Whh1, bih1, bhh1,
                                 fc1W, fc1b, fc2W, fc2b, fc3W, fc3b,
                                 (float*)d_out, out_size);
}

// round 12
// speedup vs baseline: 1.9084x; 1.9084x over previous
#include <cuda_runtime.h>
#include <math.h>

// Problem constants
#define Bv 4
#define Nv 8192
#define Sv 12
#define Lv 5
#define Ev 131072
#define CAP 128
#define BN (Bv*Nv)        // 32768 sequences
#define FSZ (Bv*Nv*Sv)    // floats per feature map

// ---------------- scratch ----------------
__device__ float g_xpA[FSZ], g_xpB[FSZ];
__device__ float g_c1A[FSZ], g_c1B[FSZ];
__device__ float g_c2A[FSZ], g_c2B[FSZ];
__device__ float g_c4A[FSZ], g_c4B[FSZ];
__device__ float g_c5A[FSZ], g_c5B[FSZ];

__device__ int g_fill [2][Nv];
__device__ int g_ci   [2][Nv*CAP];
__device__ int g_ucnt [2][Nv];
__device__ int g_uci  [2][Nv*CAP];
__device__ int g_mult [2][Nv*CAP];
__device__ int g_rfill[2][Nv];
__device__ int g_reid [2][Nv*CAP];

__device__ float g_p[2][Nv];          // per paired-stage slot
__device__ float g_q[2][Nv];
__device__ float g_w[2][Nv*CAP];
__device__ float g_esum[4][Bv*Sv];    // per-stage-slot rank-1 correction

__device__ __forceinline__ const float* bufA(int id) {
    switch (id) { case 0: return g_xpA; case 1: return g_c1A; case 2: return g_c2A;
                  case 3: return g_c4A; default: return g_c5A; }
}
__device__ __forceinline__ float* bufAw(int id) {
    switch (id) { case 0: return g_xpA; case 1: return g_c1A; case 2: return g_c2A;
                  case 3: return g_c4A; default: return g_c5A; }
}
__device__ __forceinline__ float* bufBw(int id) {
    switch (id) { case 0: return g_xpB; case 1: return g_c1B; case 2: return g_c2B;
                  case 3: return g_c4B; default: return g_c5B; }
}

// single-MUFU activations (sm_75+ tanh.approx)
__device__ __forceinline__ float tanh_ap(float x) {
    float y;
    asm("tanh.approx.f32 %0, %1;" : "=f"(y) : "f"(x));
    return y;
}
__device__ __forceinline__ float sigmf(float x) {
    return 0.5f * tanh_ap(0.5f * x) + 0.5f;
}

// ---------------- init: transpose + all zero fills ----------------
__global__ void k_init(const float* __restrict__ x) {
    int idx = blockIdx.x * blockDim.x + threadIdx.x;
    if (idx < Nv) {
        g_fill[0][idx] = 0; g_fill[1][idx] = 0;
        g_rfill[0][idx] = 0; g_rfill[1][idx] = 0;
    }
    if (idx < 4 * Bv * Sv) ((float*)g_esum)[idx] = 0.0f;
    if (idx >= FSZ) return;
    int n = idx % Nv;
    int r = idx / Nv;
    int s = r % Sv;
    int b = r / Sv;
    float v = x[idx];
    g_xpA[(b * Nv + n) * Sv + s] = v;
    g_xpB[s * BN + b * Nv + n]   = v;
}

// both edge lists in one launch
__global__ void k_bucket2(const int* __restrict__ e1, const int* __restrict__ e2) {
    int k = blockIdx.x * blockDim.x + threadIdx.x;
    if (k >= 2 * Ev) return;
    int lid = k >= Ev;
    int kk = k - lid * Ev;
    const int* ed = lid ? e2 : e1;
    int i = ed[kk];
    int j = ed[Ev + kk];
    int pos = atomicAdd(&g_fill[lid][j], 1);
    if (pos < CAP) g_ci[lid][j * CAP + pos] = i;
}

// warp-per-column dedup + fused row-CSR build + fused pq for pair A
#define DWPB 8
#define NDBLK ((2 * Nv) / DWPB)
__global__ void k_dedup2(const float* __restrict__ g1W, const float* __restrict__ g1a,
                         const float* __restrict__ g2W, const float* __restrict__ g2a) {
    if (blockIdx.x >= NDBLK) {
        // ---- pq for pair A: slot0 = g1 on xp, slot1 = g2 on xp ----
        __shared__ float wa[2][Sv], wb[2][Sv];
        int t = threadIdx.x;
        if (t < Sv) {
            float s1 = 0.f, s2 = 0.f;
            #pragma unroll
            for (int u = 0; u < Sv; u++) {
                float w = g1W[t * Sv + u];
                s1 += w * g1a[u];
                s2 += w * g1a[Sv + u];
            }
            wa[0][t] = s1; wb[0][t] = s2;
        } else if (t >= 32 && t < 32 + Sv) {
            int tt = t - 32;
            float s1 = 0.f, s2 = 0.f;
            #pragma unroll
            for (int u = 0; u < Sv; u++) {
                float w = g2W[tt * Sv + u];
                s1 += w * g2a[u];
                s2 += w * g2a[Sv + u];
            }
            wa[1][tt] = s1; wb[1][tt] = s2;
        }
        __syncthreads();
        int i = (blockIdx.x - NDBLK) * blockDim.x + threadIdx.x;
        if (i >= Nv) return;
        float pA = 0.f, qA = 0.f, pB = 0.f, qB = 0.f;
        #pragma unroll
        for (int s = 0; s < Sv; s++) {
            float v = g_xpA[i * Sv + s];
            pA += v * wa[0][s]; qA += v * wb[0][s];
            pB += v * wa[1][s]; qB += v * wb[1][s];
        }
        g_p[0][i] = pA; g_q[0][i] = qA;
        g_p[1][i] = pB; g_q[1][i] = qB;
        return;
    }

    __shared__ int s_ci[DWPB][CAP];
    int warp = threadIdx.x >> 5;
    int lane = threadIdx.x & 31;
    int jj = blockIdx.x * DWPB + warp;
    int lid = jj >= Nv;
    int j = jj - lid * Nv;
    int k = min(g_fill[lid][j], CAP);
    const int* ci = g_ci[lid] + j * CAP;
    for (int t = lane; t < k; t += 32) s_ci[warp][t] = ci[t];
    __syncwarp();
    int* uci = g_uci[lid] + j * CAP;
    int* mlt = g_mult[lid] + j * CAP;
    int base = 0;
    for (int c = 0; c < k; c += 32) {
        int idx = c + lane;
        bool valid = idx < k;
        int i = valid ? s_ci[warp][idx] : -1;
        bool leader = valid;
        int mult = 0;
        if (valid) {
            for (int t = 0; t < idx; t++)
                if (s_ci[warp][t] == i) { leader = false; break; }
            if (leader)
                for (int t = idx; t < k; t++)
                    if (s_ci[warp][t] == i) mult++;
        }
        unsigned bal = __ballot_sync(0xFFFFFFFF, leader);
        if (leader) {
            int pos = base + __popc(bal & ((1u << lane) - 1));
            uci[pos] = i; mlt[pos] = mult;
            int rp = atomicAdd(&g_rfill[lid][i], 1);
            if (rp < CAP) g_reid[lid][i * CAP + rp] = j * CAP + pos;
        }
        base += __popc(bal);
    }
    if (lane == 0) g_ucnt[lid][j] = base;
}

// warp-per-column softmax; slot A uses list lidA, slot B list lidB
__global__ void k_colw2(int lidA, int lidB, int xidA, int xidB, int esumBase,
                        const float* __restrict__ lwA, const float* __restrict__ lbA,
                        const float* __restrict__ lwB, const float* __restrict__ lbB) {
    int warp = threadIdx.x >> 5;
    int lane = threadIdx.x & 31;
    int jj = blockIdx.x * (blockDim.x >> 5) + warp;
    if (jj >= 2 * Nv) return;
    int sid = jj >= Nv;
    int j = jj - sid * Nv;
    int lid = sid ? lidB : lidA;
    int u = g_ucnt[lid][j];
    if (u == 0) {
        const float* X = bufA(sid ? xidB : xidA);
        for (int t = lane; t < Bv * Sv; t += 32) {
            int b = t / Sv, s = t - b * Sv;
            atomicAdd(&g_esum[esumBase + sid][t], X[(b * Nv + j) * Sv + s]);
        }
        return;
    }
    const int* uci = g_uci[lid] + j * CAP;
    const int* mlt = g_mult[lid] + j * CAP;
    float* wv = g_w[sid] + j * CAP;
    float qj = g_q[sid][j];
    float lwv = sid ? lwB[0] : lwA[0];
    float lbv = sid ? lbB[0] : lbA[0];
    float vals[4];
    int cnt = 0;
    float m = -1e30f;
    for (int t = lane; t < u; t += 32) {
        float e = g_p[sid][uci[t]] + qj;
        e = (e > 0.f) ? e : 0.2f * e;
        float val = (float)mlt[t] * (e * lwv + lbv);
        vals[cnt++] = val;
        m = fmaxf(m, val);
    }
    #pragma unroll
    for (int o = 16; o; o >>= 1) m = fmaxf(m, __shfl_xor_sync(0xFFFFFFFF, m, o));
    float den = 0.f;
    for (int c = 0; c < cnt; c++) {
        vals[c] = __expf(vals[c] - m);
        den += vals[c];
    }
    #pragma unroll
    for (int o = 16; o; o >>= 1) den += __shfl_xor_sync(0xFFFFFFFF, den, o);
    float inv = 1.0f / den;
    cnt = 0;
    for (int t = lane; t < u; t += 32) wv[t] = vals[cnt++] * inv;
}

// gather SpMM + fused GCN; 8 threads per (slot,b,i), shuffle reduction.
// unroll-2 on the neighbor loop for MLP; vectorized float4 epilogue stores.
#define GSUB 8
__global__ void k_gather2(int lidA, int lidB, int xidA, int xidB,
                          int outA, int outB, int esumBase, int doPQ,
                          const float* __restrict__ gcnW,
                          const float* __restrict__ gcnb,
                          const float* __restrict__ g1W, const float* __restrict__ g1a,
                          const float* __restrict__ g2W, const float* __restrict__ g2a) {
    __shared__ float sW[Sv * Sv], sb[Sv];
    __shared__ float wa[2][Sv], wb[2][Sv];
    int tx = threadIdx.x;
    if (tx < Sv * Sv) sW[tx] = gcnW[tx];
    if (tx < Sv) sb[tx] = gcnb[tx];
    if (doPQ) {
        if (tx < Sv) {
            float s1 = 0.f, s2 = 0.f;
            #pragma unroll
            for (int u = 0; u < Sv; u++) {
                float w = g1W[tx * Sv + u];
                s1 += w * g1a[u];
                s2 += w * g1a[Sv + u];
            }
            wa[0][tx] = s1; wb[0][tx] = s2;
        } else if (tx >= 32 && tx < 32 + Sv) {
            int tt = tx - 32;
            float s1 = 0.f, s2 = 0.f;
            #pragma unroll
            for (int u = 0; u < Sv; u++) {
                float w = g2W[tt * Sv + u];
                s1 += w * g2a[u];
                s2 += w * g2a[Sv + u];
            }
            wa[1][tt] = s1; wb[1][tt] = s2;
        }
    }
    __syncthreads();

    int gtid = blockIdx.x * blockDim.x + threadIdx.x;
    int gid = gtid / GSUB;      // (slot,b,i) id
    int sub = gtid % GSUB;
    if (gid >= 2 * BN) return;
    int sid = gid >= BN;
    int rem = gid - sid * BN;
    int i = rem & (Nv - 1);
    int b = rem >> 13;
    int lid = sid ? lidB : lidA;

    const float* X = bufA(sid ? xidB : xidA);
    const int* reid = g_reid[lid] + i * CAP;
    const float* wv = g_w[sid];
    int deg = min(g_rfill[lid][i], CAP);

    float z[Sv];
    #pragma unroll
    for (int s = 0; s < Sv; s++) z[s] = 0.f;

    #pragma unroll 2
    for (int t = sub; t < deg; t += GSUB) {
        int eid = reid[t];
        float w = wv[eid];
        int j = eid >> 7;   // CAP = 128
        const float4* xr = (const float4*)(X + (b * Nv + j) * Sv);
        float4 v0 = xr[0], v1 = xr[1], v2 = xr[2];
        z[0] += w * v0.x; z[1] += w * v0.y; z[2]  += w * v0.z; z[3]  += w * v0.w;
        z[4] += w * v1.x; z[5] += w * v1.y; z[6]  += w * v1.z; z[7]  += w * v1.w;
        z[8] += w * v2.x; z[9] += w * v2.y; z[10] += w * v2.z; z[11] += w * v2.w;
    }
    #pragma unroll
    for (int o = 1; o < GSUB; o <<= 1) {
        #pragma unroll
        for (int s = 0; s < Sv; s++)
            z[s] += __shfl_xor_sync(0xFFFFFFFF, z[s], o);
    }
    if (sub != 0) return;

    #pragma unroll
    for (int s = 0; s < Sv; s++)
        z[s] += g_esum[esumBase + sid][b * Sv + s] * (1.0f / (float)Nv);

    float* OA = bufAw(sid ? outB : outA);
    float* OB = bufBw(sid ? outB : outA);
    int tid = b * Nv + i;
    float yv[Sv];
    float pN = 0.f, qN = 0.f;
    #pragma unroll
    for (int s = 0; s < Sv; s++) {
        float y = sb[s];
        #pragma unroll
        for (int t = 0; t < Sv; t++) y += z[t] * sW[s * Sv + t];
        y = (y > 0.f) ? y : 0.01f * y;
        yv[s] = y;
        OB[s * BN + tid] = y;
        pN += y * wa[sid][s];
        qN += y * wb[sid][s];
    }
    // vectorized A-layout store (rows are 16B-aligned: tid*48 bytes)
    float4* oa4 = (float4*)(OA + tid * Sv);
    oa4[0] = make_float4(yv[0], yv[1], yv[2],  yv[3]);
    oa4[1] = make_float4(yv[4], yv[5], yv[6],  yv[7]);
    oa4[2] = make_float4(yv[8], yv[9], yv[10], yv[11]);

    if (doPQ && b == 0) {
        g_p[sid][i] = pN;
        g_q[sid][i] = qN;
    }
}

// ---------------- fused 2-layer LSTM + TPA head ----------------
__global__ void __launch_bounds__(128)
k_lstm(const float* __restrict__ Wih0, const float* __restrict__ Whh0,
       const float* __restrict__ bih0, const float* __restrict__ bhh0,
       const float* __restrict__ Wih1, const float* __restrict__ Whh1,
       const float* __restrict__ bih1, const float* __restrict__ bhh1,
       const float* __restrict__ fc1W, const float* __restrict__ fc1b,
       const float* __restrict__ fc2W, const float* __restrict__ fc2b,
       const float* __restrict__ fc3W, const float* __restrict__ fc3b,
       float* __restrict__ out, int out_size) {
    __shared__ float sWih0[100], sWhh0[100], sB0[20];
    __shared__ float sWih1[100], sWhh1[100], sB1[20];
    __shared__ float sF1[176], sF1b[16], sF2[80], sF2b[5], sF3[21], sF3b;
    int t = threadIdx.x;
    for (int i = t; i < 100; i += blockDim.x) {
        sWih0[i] = Wih0[i]; sWhh0[i] = Whh0[i];
        sWih1[i] = Wih1[i]; sWhh1[i] = Whh1[i];
    }
    for (int i = t; i < 20; i += blockDim.x) {
        sB0[i] = bih0[i] + bhh0[i];
        sB1[i] = bih1[i] + bhh1[i];
    }
    for (int i = t; i < 176; i += blockDim.x) sF1[i] = fc1W[i];
    for (int i = t; i < 80;  i += blockDim.x) sF2[i] = fc2W[i];
    for (int i = t; i < 21;  i += blockDim.x) sF3[i] = fc3W[i];
    for (int i = t; i < 16;  i += blockDim.x) sF1b[i] = fc1b[i];
    for (int i = t; i < 5;   i += blockDim.x) sF2b[i] = fc2b[i];
    if (t == 0) sF3b = fc3b[0];
    __syncthreads();

    int seq = blockIdx.x * blockDim.x + threadIdx.x;
    if (seq >= BN) return;

    float h0[Lv], c0[Lv], h1[Lv], c1l[Lv];
    #pragma unroll
    for (int l = 0; l < Lv; l++) { h0[l]=0.f; c0[l]=0.f; h1[l]=0.f; c1l[l]=0.f; }

    float Hc[Lv][16];
    #pragma unroll
    for (int l = 0; l < Lv; l++)
        #pragma unroll
        for (int k = 0; k < 16; k++)
            Hc[l][k] = sF1b[k];

    #pragma unroll 1
    for (int tt = 0; tt < Sv; tt++) {
        float xv[Lv];
        xv[0] = g_xpB[tt * BN + seq];
        xv[1] = g_c1B[tt * BN + seq];
        xv[2] = g_c2B[tt * BN + seq];
        xv[3] = g_c4B[tt * BN + seq];
        xv[4] = g_c5B[tt * BN + seq];

        float z[20];
        #pragma unroll
        for (int g = 0; g < 20; g++) {
            float zz = sB0[g];
            #pragma unroll
            for (int l = 0; l < Lv; l++)
                zz += sWih0[g * Lv + l] * xv[l] + sWhh0[g * Lv + l] * h0[l];
            z[g] = zz;
        }
        #pragma unroll
        for (int l = 0; l < Lv; l++) {
            float ig = sigmf(z[l]);
            float fg = sigmf(z[5 + l]);
            float gg = tanh_ap(z[10 + l]);
            float og = sigmf(z[15 + l]);
            c0[l] = fg * c0[l] + ig * gg;
            h0[l] = og * tanh_ap(c0[l]);
        }
        #pragma unroll
        for (int g = 0; g < 20; g++) {
            float zz = sB1[g];
            #pragma unroll
            for (int l = 0; l < Lv; l++)
                zz += sWih1[g * Lv + l] * h0[l] + sWhh1[g * Lv + l] * h1[l];
            z[g] = zz;
        }
        #pragma unroll
        for (int l = 0; l < Lv; l++) {
            float ig = sigmf(z[l]);
            float fg = sigmf(z[5 + l]);
            float gg = tanh_ap(z[10 + l]);
            float og = sigmf(z[15 + l]);
            c1l[l] = fg * c1l[l] + ig * gg;
            h1[l] = og * tanh_ap(c1l[l]);
        }
        if (tt < Sv - 1) {
            #pragma unroll
            for (int l = 0; l < Lv; l++) {
                float hv = h1[l];
                #pragma unroll
                for (int k = 0; k < 16; k++)
                    Hc[l][k] += hv * sF1[k * (Sv - 1) + tt];
            }
        }
    }

    float ht[Lv];
    #pragma unroll
    for (int m = 0; m < Lv; m++) ht[m] = h1[m];

    float av[Lv];
    #pragma unroll
    for (int l = 0; l < Lv; l++) {
        float s = 0.f;
        #pragma unroll
        for (int m = 0; m < Lv; m++) {
            float hn = sF2b[m];
            #pragma unroll
            for (int k = 0; k < 16; k++) hn += Hc[l][k] * sF2[m * 16 + k];
            s += hn * ht[m];
        }
        av[l] = sigmf(s);
    }

    float y = sF3b;
    #pragma unroll
    for (int k = 0; k < 16; k++) {
        float vt = 0.f;
        #pragma unroll
        for (int l = 0; l < Lv; l++) vt += av[l] * Hc[l][k];
        y += vt * sF3[k];
    }
    #pragma unroll
    for (int m = 0; m < Lv; m++) y += ht[m] * sF3[16 + m];

    out[seq] = y;
    if (BN + seq * Lv + (Lv - 1) < out_size) {
        #pragma unroll
        for (int l = 0; l < Lv; l++)
            out[BN + seq * Lv + l] = av[l];
    }
}

// ---------------- launcher ----------------
extern "C" void kernel_launch(void* const* d_in, const int* in_sizes, int n_in,
                              void* d_out, int out_size) {
    const float* x    = (const float*)d_in[0];
    const int*   e1   = (const int*)  d_in[1];
    const int*   e2   = (const int*)  d_in[2];
    const float* g1W  = (const float*)d_in[3];
    const float* g1a  = (const float*)d_in[4];
    const float* g1lw = (const float*)d_in[5];
    const float* g1lb = (const float*)d_in[6];
    const float* g2W  = (const float*)d_in[7];
    const float* g2a  = (const float*)d_in[8];
    const float* g2lw = (const float*)d_in[9];
    const float* g2lb = (const float*)d_in[10];
    const float* gcnW = (const float*)d_in[11];
    const float* gcnb = (const float*)d_in[12];
    const float* Wih0 = (const float*)d_in[13];
    const float* Whh0 = (const float*)d_in[14];
    const float* bih0 = (const float*)d_in[15];
    const float* bhh0 = (const float*)d_in[16];
    const float* Wih1 = (const float*)d_in[17];
    const float* Whh1 = (const float*)d_in[18];
    const float* bih1 = (const float*)d_in[19];
    const float* bhh1 = (const float*)d_in[20];
    const float* fc1W = (const float*)d_in[21];
    const float* fc1b = (const float*)d_in[22];
    const float* fc2W = (const float*)d_in[23];
    const float* fc2b = (const float*)d_in[24];
    const float* fc3W = (const float*)d_in[25];
    const float* fc3b = (const float*)d_in[26];

    const int TB = 256;
    k_init<<<(FSZ + TB - 1) / TB, TB>>>(x);
    k_bucket2<<<(2 * Ev + TB - 1) / TB, TB>>>(e1, e2);
    // dedup + fused rowbuild + fused pq for pair A
    k_dedup2<<<NDBLK + (Nv + TB - 1) / TB, TB>>>(g1W, g1a, g2W, g2a);

    // pair A: stage0 (list0, xp -> c1) + stage2 (list1, xp -> c4)
    k_colw2<<<(2 * Nv) / 8, 256>>>(0, 1, 0, 0, 0, g1lw, g1lb, g2lw, g2lb);
    k_gather2<<<(2 * BN * GSUB) / TB, TB>>>(0, 1, 0, 0, 1, 3, 0, 1,
                                            gcnW, gcnb, g1W, g1a, g2W, g2a);

    // pair B: stage1 (list0, c1 -> c2) + stage3 (list1, c4 -> c5)
    k_colw2<<<(2 * Nv) / 8, 256>>>(0, 1, 1, 3, 2, g1lw, g1lb, g2lw, g2lb);
    k_gather2<<<(2 * BN * GSUB) / TB, TB>>>(0, 1, 1, 3, 2, 5, 2, 0,
                                            gcnW, gcnb, g1W, g1a, g2W, g2a);

    k_lstm<<<(BN + 127) / 128, 128>>>(Wih0, Whh0, bih0, bhh0,
                                      Wih1, Whh1, bih1, bhh1,
                                      fc1W, fc1b, fc2W, fc2b, fc3W, fc3b,
                                      (float*)d_out, out_size);
}

// round 13
// speedup vs baseline: 2.4151x; 1.2655x over previous
#include <cuda_runtime.h>
#include <math.h>

// Problem constants
#define Bv 4
#define Nv 8192
#define Sv 12
#define Lv 5
#define Ev 131072
#define CAP 128
#define BN (Bv*Nv)        // 32768 sequences
#define FSZ (Bv*Nv*Sv)    // floats per feature map

// ---------------- scratch ----------------
__device__ float g_xpA[FSZ], g_xpB[FSZ];
__device__ float g_c1A[FSZ], g_c1B[FSZ];
__device__ float g_c2A[FSZ], g_c2B[FSZ];
__device__ float g_c4A[FSZ], g_c4B[FSZ];
__device__ float g_c5A[FSZ], g_c5B[FSZ];

__device__ int g_fill [2][Nv];
__device__ int g_ci   [2][Nv*CAP];
__device__ int g_ucnt [2][Nv];
__device__ int g_uci  [2][Nv*CAP];
__device__ int g_mult [2][Nv*CAP];
__device__ int g_rfill[2][Nv];
__device__ int g_reid [2][Nv*CAP];

__device__ float g_p[2][Nv];          // per paired-stage slot
__device__ float g_q[2][Nv];
__device__ float g_w[2][Nv*CAP];
__device__ float g_esum[4][Bv*Sv];    // per-stage-slot rank-1 correction

__device__ __forceinline__ const float* bufA(int id) {
    switch (id) { case 0: return g_xpA; case 1: return g_c1A; case 2: return g_c2A;
                  case 3: return g_c4A; default: return g_c5A; }
}
__device__ __forceinline__ float* bufAw(int id) {
    switch (id) { case 0: return g_xpA; case 1: return g_c1A; case 2: return g_c2A;
                  case 3: return g_c4A; default: return g_c5A; }
}
__device__ __forceinline__ float* bufBw(int id) {
    switch (id) { case 0: return g_xpB; case 1: return g_c1B; case 2: return g_c2B;
                  case 3: return g_c4B; default: return g_c5B; }
}

// single-MUFU activations (sm_75+ tanh.approx)
__device__ __forceinline__ float tanh_ap(float x) {
    float y;
    asm("tanh.approx.f32 %0, %1;" : "=f"(y) : "f"(x));
    return y;
}
__device__ __forceinline__ float sigmf(float x) {
    return 0.5f * tanh_ap(0.5f * x) + 0.5f;
}

// ---------------- init: transpose + all zero fills ----------------
__global__ void k_init(const float* __restrict__ x) {
    int idx = blockIdx.x * blockDim.x + threadIdx.x;
    if (idx < Nv) {
        g_fill[0][idx] = 0; g_fill[1][idx] = 0;
        g_rfill[0][idx] = 0; g_rfill[1][idx] = 0;
    }
    if (idx < 4 * Bv * Sv) ((float*)g_esum)[idx] = 0.0f;
    if (idx >= FSZ) return;
    int n = idx % Nv;
    int r = idx / Nv;
    int s = r % Sv;
    int b = r / Sv;
    float v = x[idx];
    g_xpA[(b * Nv + n) * Sv + s] = v;
    g_xpB[s * BN + b * Nv + n]   = v;
}

// both edge lists in one launch
__global__ void k_bucket2(const int* __restrict__ e1, const int* __restrict__ e2) {
    int k = blockIdx.x * blockDim.x + threadIdx.x;
    if (k >= 2 * Ev) return;
    int lid = k >= Ev;
    int kk = k - lid * Ev;
    const int* ed = lid ? e2 : e1;
    int i = ed[kk];
    int j = ed[Ev + kk];
    int pos = atomicAdd(&g_fill[lid][j], 1);
    if (pos < CAP) g_ci[lid][j * CAP + pos] = i;
}

// warp-per-column dedup + fused row-CSR build + fused pq for pair A
#define DWPB 8
#define NDBLK ((2 * Nv) / DWPB)
__global__ void k_dedup2(const float* __restrict__ g1W, const float* __restrict__ g1a,
                         const float* __restrict__ g2W, const float* __restrict__ g2a) {
    if (blockIdx.x >= NDBLK) {
        // ---- pq for pair A: slot0 = g1 on xp, slot1 = g2 on xp ----
        __shared__ float wa[2][Sv], wb[2][Sv];
        int t = threadIdx.x;
        if (t < Sv) {
            float s1 = 0.f, s2 = 0.f;
            #pragma unroll
            for (int u = 0; u < Sv; u++) {
                float w = g1W[t * Sv + u];
                s1 += w * g1a[u];
                s2 += w * g1a[Sv + u];
            }
            wa[0][t] = s1; wb[0][t] = s2;
        } else if (t >= 32 && t < 32 + Sv) {
            int tt = t - 32;
            float s1 = 0.f, s2 = 0.f;
            #pragma unroll
            for (int u = 0; u < Sv; u++) {
                float w = g2W[tt * Sv + u];
                s1 += w * g2a[u];
                s2 += w * g2a[Sv + u];
            }
            wa[1][tt] = s1; wb[1][tt] = s2;
        }
        __syncthreads();
        int i = (blockIdx.x - NDBLK) * blockDim.x + threadIdx.x;
        if (i >= Nv) return;
        float pA = 0.f, qA = 0.f, pB = 0.f, qB = 0.f;
        #pragma unroll
        for (int s = 0; s < Sv; s++) {
            float v = g_xpA[i * Sv + s];
            pA += v * wa[0][s]; qA += v * wb[0][s];
            pB += v * wa[1][s]; qB += v * wb[1][s];
        }
        g_p[0][i] = pA; g_q[0][i] = qA;
        g_p[1][i] = pB; g_q[1][i] = qB;
        return;
    }

    __shared__ int s_ci[DWPB][CAP];
    int warp = threadIdx.x >> 5;
    int lane = threadIdx.x & 31;
    int jj = blockIdx.x * DWPB + warp;
    int lid = jj >= Nv;
    int j = jj - lid * Nv;
    int k = min(g_fill[lid][j], CAP);
    const int* ci = g_ci[lid] + j * CAP;
    for (int t = lane; t < k; t += 32) s_ci[warp][t] = ci[t];
    __syncwarp();
    int* uci = g_uci[lid] + j * CAP;
    int* mlt = g_mult[lid] + j * CAP;
    int base = 0;
    for (int c = 0; c < k; c += 32) {
        int idx = c + lane;
        bool valid = idx < k;
        int i = valid ? s_ci[warp][idx] : -1;
        bool leader = valid;
        int mult = 0;
        if (valid) {
            for (int t = 0; t < idx; t++)
                if (s_ci[warp][t] == i) { leader = false; break; }
            if (leader)
                for (int t = idx; t < k; t++)
                    if (s_ci[warp][t] == i) mult++;
        }
        unsigned bal = __ballot_sync(0xFFFFFFFF, leader);
        if (leader) {
            int pos = base + __popc(bal & ((1u << lane) - 1));
            uci[pos] = i; mlt[pos] = mult;
            int rp = atomicAdd(&g_rfill[lid][i], 1);
            if (rp < CAP) g_reid[lid][i * CAP + rp] = j * CAP + pos;
        }
        base += __popc(bal);
    }
    if (lane == 0) g_ucnt[lid][j] = base;
}

// warp-per-column softmax; slot A uses list lidA, slot B list lidB
__global__ void k_colw2(int lidA, int lidB, int xidA, int xidB, int esumBase,
                        const float* __restrict__ lwA, const float* __restrict__ lbA,
                        const float* __restrict__ lwB, const float* __restrict__ lbB) {
    int warp = threadIdx.x >> 5;
    int lane = threadIdx.x & 31;
    int jj = blockIdx.x * (blockDim.x >> 5) + warp;
    if (jj >= 2 * Nv) return;
    int sid = jj >= Nv;
    int j = jj - sid * Nv;
    int lid = sid ? lidB : lidA;
    int u = g_ucnt[lid][j];
    if (u == 0) {
        const float* X = bufA(sid ? xidB : xidA);
        for (int t = lane; t < Bv * Sv; t += 32) {
            int b = t / Sv, s = t - b * Sv;
            atomicAdd(&g_esum[esumBase + sid][t], X[(b * Nv + j) * Sv + s]);
        }
        return;
    }
    const int* uci = g_uci[lid] + j * CAP;
    const int* mlt = g_mult[lid] + j * CAP;
    float* wv = g_w[sid] + j * CAP;
    float qj = g_q[sid][j];
    float lwv = sid ? lwB[0] : lwA[0];
    float lbv = sid ? lbB[0] : lbA[0];
    float vals[4];
    int cnt = 0;
    float m = -1e30f;
    for (int t = lane; t < u; t += 32) {
        float e = g_p[sid][uci[t]] + qj;
        e = (e > 0.f) ? e : 0.2f * e;
        float val = (float)mlt[t] * (e * lwv + lbv);
        vals[cnt++] = val;
        m = fmaxf(m, val);
    }
    #pragma unroll
    for (int o = 16; o; o >>= 1) m = fmaxf(m, __shfl_xor_sync(0xFFFFFFFF, m, o));
    float den = 0.f;
    for (int c = 0; c < cnt; c++) {
        vals[c] = __expf(vals[c] - m);
        den += vals[c];
    }
    #pragma unroll
    for (int o = 16; o; o >>= 1) den += __shfl_xor_sync(0xFFFFFFFF, den, o);
    float inv = 1.0f / den;
    cnt = 0;
    for (int t = lane; t < u; t += 32) wv[t] = vals[cnt++] * inv;
}

// gather SpMM + fused GCN; 8 threads per (slot,b,i), shuffle reduction.
#define GSUB 8
__global__ void k_gather2(int lidA, int lidB, int xidA, int xidB,
                          int outA, int outB, int esumBase, int doPQ,
                          const float* __restrict__ gcnW,
                          const float* __restrict__ gcnb,
                          const float* __restrict__ g1W, const float* __restrict__ g1a,
                          const float* __restrict__ g2W, const float* __restrict__ g2a) {
    __shared__ float sW[Sv * Sv], sb[Sv];
    __shared__ float wa[2][Sv], wb[2][Sv];
    int tx = threadIdx.x;
    if (tx < Sv * Sv) sW[tx] = gcnW[tx];
    if (tx < Sv) sb[tx] = gcnb[tx];
    if (doPQ) {
        if (tx < Sv) {
            float s1 = 0.f, s2 = 0.f;
            #pragma unroll
            for (int u = 0; u < Sv; u++) {
                float w = g1W[tx * Sv + u];
                s1 += w * g1a[u];
                s2 += w * g1a[Sv + u];
            }
            wa[0][tx] = s1; wb[0][tx] = s2;
        } else if (tx >= 32 && tx < 32 + Sv) {
            int tt = tx - 32;
            float s1 = 0.f, s2 = 0.f;
            #pragma unroll
            for (int u = 0; u < Sv; u++) {
                float w = g2W[tt * Sv + u];
                s1 += w * g2a[u];
                s2 += w * g2a[Sv + u];
            }
            wa[1][tt] = s1; wb[1][tt] = s2;
        }
    }
    __syncthreads();

    int gtid = blockIdx.x * blockDim.x + threadIdx.x;
    int gid = gtid / GSUB;      // (slot,b,i) id
    int sub = gtid % GSUB;
    if (gid >= 2 * BN) return;
    int sid = gid >= BN;
    int rem = gid - sid * BN;
    int i = rem & (Nv - 1);
    int b = rem >> 13;
    int lid = sid ? lidB : lidA;

    const float* X = bufA(sid ? xidB : xidA);
    const int* reid = g_reid[lid] + i * CAP;
    const float* wv = g_w[sid];
    int deg = min(g_rfill[lid][i], CAP);

    float z[Sv];
    #pragma unroll
    for (int s = 0; s < Sv; s++) z[s] = 0.f;

    #pragma unroll 2
    for (int t = sub; t < deg; t += GSUB) {
        int eid = reid[t];
        float w = wv[eid];
        int j = eid >> 7;   // CAP = 128
        const float4* xr = (const float4*)(X + (b * Nv + j) * Sv);
        float4 v0 = xr[0], v1 = xr[1], v2 = xr[2];
        z[0] += w * v0.x; z[1] += w * v0.y; z[2]  += w * v0.z; z[3]  += w * v0.w;
        z[4] += w * v1.x; z[5] += w * v1.y; z[6]  += w * v1.z; z[7]  += w * v1.w;
        z[8] += w * v2.x; z[9] += w * v2.y; z[10] += w * v2.z; z[11] += w * v2.w;
    }
    #pragma unroll
    for (int o = 1; o < GSUB; o <<= 1) {
        #pragma unroll
        for (int s = 0; s < Sv; s++)
            z[s] += __shfl_xor_sync(0xFFFFFFFF, z[s], o);
    }
    if (sub != 0) return;

    #pragma unroll
    for (int s = 0; s < Sv; s++)
        z[s] += g_esum[esumBase + sid][b * Sv + s] * (1.0f / (float)Nv);

    float* OA = bufAw(sid ? outB : outA);
    float* OB = bufBw(sid ? outB : outA);
    int tid = b * Nv + i;
    float yv[Sv];
    float pN = 0.f, qN = 0.f;
    #pragma unroll
    for (int s = 0; s < Sv; s++) {
        float y = sb[s];
        #pragma unroll
        for (int t = 0; t < Sv; t++) y += z[t] * sW[s * Sv + t];
        y = (y > 0.f) ? y : 0.01f * y;
        yv[s] = y;
        OB[s * BN + tid] = y;
        pN += y * wa[sid][s];
        qN += y * wb[sid][s];
    }
    // vectorized A-layout store (rows are 16B-aligned: tid*48 bytes)
    float4* oa4 = (float4*)(OA + tid * Sv);
    oa4[0] = make_float4(yv[0], yv[1], yv[2],  yv[3]);
    oa4[1] = make_float4(yv[4], yv[5], yv[6],  yv[7]);
    oa4[2] = make_float4(yv[8], yv[9], yv[10], yv[11]);

    if (doPQ && b == 0) {
        g_p[sid][i] = pN;
        g_q[sid][i] = qN;
    }
}

// ---------------- fused 2-layer LSTM + TPA head ----------------
// v2: per-timestep h1 staged to SHARED memory; Hc[5][16] computed post-loop.
// Keeps the in-loop live set small (~50 regs) so nothing spills to local.
#define LTB 128
__global__ void __launch_bounds__(LTB)
k_lstm(const float* __restrict__ Wih0, const float* __restrict__ Whh0,
       const float* __restrict__ bih0, const float* __restrict__ bhh0,
       const float* __restrict__ Wih1, const float* __restrict__ Whh1,
       const float* __restrict__ bih1, const float* __restrict__ bhh1,
       const float* __restrict__ fc1W, const float* __restrict__ fc1b,
       const float* __restrict__ fc2W, const float* __restrict__ fc2b,
       const float* __restrict__ fc3W, const float* __restrict__ fc3b,
       float* __restrict__ out, int out_size) {
    __shared__ float sWih0[100], sWhh0[100], sB0[20];
    __shared__ float sWih1[100], sWhh1[100], sB1[20];
    __shared__ float sF1[176], sF1b[16], sF2[80], sF2b[5], sF3[21], sF3b;
    __shared__ float sH[(Sv - 1) * Lv * LTB];   // h1 per timestep (0..10), per thread
    int t = threadIdx.x;
    for (int i = t; i < 100; i += blockDim.x) {
        sWih0[i] = Wih0[i]; sWhh0[i] = Whh0[i];
        sWih1[i] = Wih1[i]; sWhh1[i] = Whh1[i];
    }
    for (int i = t; i < 20; i += blockDim.x) {
        sB0[i] = bih0[i] + bhh0[i];
        sB1[i] = bih1[i] + bhh1[i];
    }
    for (int i = t; i < 176; i += blockDim.x) sF1[i] = fc1W[i];
    for (int i = t; i < 80;  i += blockDim.x) sF2[i] = fc2W[i];
    for (int i = t; i < 21;  i += blockDim.x) sF3[i] = fc3W[i];
    for (int i = t; i < 16;  i += blockDim.x) sF1b[i] = fc1b[i];
    for (int i = t; i < 5;   i += blockDim.x) sF2b[i] = fc2b[i];
    if (t == 0) sF3b = fc3b[0];
    __syncthreads();

    int seq = blockIdx.x * blockDim.x + threadIdx.x;
    if (seq >= BN) return;

    float h0[Lv], c0[Lv], h1[Lv], c1l[Lv];
    #pragma unroll
    for (int l = 0; l < Lv; l++) { h0[l]=0.f; c0[l]=0.f; h1[l]=0.f; c1l[l]=0.f; }

    #pragma unroll 1
    for (int tt = 0; tt < Sv; tt++) {
        float xv[Lv];
        xv[0] = g_xpB[tt * BN + seq];
        xv[1] = g_c1B[tt * BN + seq];
        xv[2] = g_c2B[tt * BN + seq];
        xv[3] = g_c4B[tt * BN + seq];
        xv[4] = g_c5B[tt * BN + seq];

        float z[20];
        #pragma unroll
        for (int g = 0; g < 20; g++) {
            float zz = sB0[g];
            #pragma unroll
            for (int l = 0; l < Lv; l++)
                zz += sWih0[g * Lv + l] * xv[l] + sWhh0[g * Lv + l] * h0[l];
            z[g] = zz;
        }
        #pragma unroll
        for (int l = 0; l < Lv; l++) {
            float ig = sigmf(z[l]);
            float fg = sigmf(z[5 + l]);
            float gg = tanh_ap(z[10 + l]);
            float og = sigmf(z[15 + l]);
            c0[l] = fg * c0[l] + ig * gg;
            h0[l] = og * tanh_ap(c0[l]);
        }
        #pragma unroll
        for (int g = 0; g < 20; g++) {
            float zz = sB1[g];
            #pragma unroll
            for (int l = 0; l < Lv; l++)
                zz += sWih1[g * Lv + l] * h0[l] + sWhh1[g * Lv + l] * h1[l];
            z[g] = zz;
        }
        #pragma unroll
        for (int l = 0; l < Lv; l++) {
            float ig = sigmf(z[l]);
            float fg = sigmf(z[5 + l]);
            float gg = tanh_ap(z[10 + l]);
            float og = sigmf(z[15 + l]);
            c1l[l] = fg * c1l[l] + ig * gg;
            h1[l] = og * tanh_ap(c1l[l]);
        }
        // stage h1 to shared (conflict-free: stride-1 across threads)
        if (tt < Sv - 1) {
            #pragma unroll
            for (int l = 0; l < Lv; l++)
                sH[(tt * Lv + l) * LTB + t] = h1[l];
        }
    }

    float ht[Lv];
    #pragma unroll
    for (int m = 0; m < Lv; m++) ht[m] = h1[m];

    // Hc[5][16] from shared h history (loop live set is now small)
    float Hc[Lv][16];
    #pragma unroll
    for (int l = 0; l < Lv; l++) {
        #pragma unroll
        for (int k = 0; k < 16; k++) Hc[l][k] = sF1b[k];
        #pragma unroll
        for (int tt = 0; tt < Sv - 1; tt++) {
            float hv = sH[(tt * Lv + l) * LTB + t];
            #pragma unroll
            for (int k = 0; k < 16; k++)
                Hc[l][k] += hv * sF1[k * (Sv - 1) + tt];
        }
    }

    float av[Lv];
    #pragma unroll
    for (int l = 0; l < Lv; l++) {
        float s = 0.f;
        #pragma unroll
        for (int m = 0; m < Lv; m++) {
            float hn = sF2b[m];
            #pragma unroll
            for (int k = 0; k < 16; k++) hn += Hc[l][k] * sF2[m * 16 + k];
            s += hn * ht[m];
        }
        av[l] = sigmf(s);
    }

    float y = sF3b;
    #pragma unroll
    for (int k = 0; k < 16; k++) {
        float vt = 0.f;
        #pragma unroll
        for (int l = 0; l < Lv; l++) vt += av[l] * Hc[l][k];
        y += vt * sF3[k];
    }
    #pragma unroll
    for (int m = 0; m < Lv; m++) y += ht[m] * sF3[16 + m];

    out[seq] = y;
    if (BN + seq * Lv + (Lv - 1) < out_size) {
        #pragma unroll
        for (int l = 0; l < Lv; l++)
            out[BN + seq * Lv + l] = av[l];
    }
}

// ---------------- launcher ----------------
extern "C" void kernel_launch(void* const* d_in, const int* in_sizes, int n_in,
                              void* d_out, int out_size) {
    const float* x    = (const float*)d_in[0];
    const int*   e1   = (const int*)  d_in[1];
    const int*   e2   = (const int*)  d_in[2];
    const float* g1W  = (const float*)d_in[3];
    const float* g1a  = (const float*)d_in[4];
    const float* g1lw = (const float*)d_in[5];
    const float* g1lb = (const float*)d_in[6];
    const float* g2W  = (const float*)d_in[7];
    const float* g2a  = (const float*)d_in[8];
    const float* g2lw = (const float*)d_in[9];
    const float* g2lb = (const float*)d_in[10];
    const float* gcnW = (const float*)d_in[11];
    const float* gcnb = (const float*)d_in[12];
    const float* Wih0 = (const float*)d_in[13];
    const float* Whh0 = (const float*)d_in[14];
    const float* bih0 = (const float*)d_in[15];
    const float* bhh0 = (const float*)d_in[16];
    const float* Wih1 = (const float*)d_in[17];
    const float* Whh1 = (const float*)d_in[18];
    const float* bih1 = (const float*)d_in[19];
    const float* bhh1 = (const float*)d_in[20];
    const float* fc1W = (const float*)d_in[21];
    const float* fc1b = (const float*)d_in[22];
    const float* fc2W = (const float*)d_in[23];
    const float* fc2b = (const float*)d_in[24];
    const float* fc3W = (const float*)d_in[25];
    const float* fc3b = (const float*)d_in[26];

    const int TB = 256;
    k_init<<<(FSZ + TB - 1) / TB, TB>>>(x);
    k_bucket2<<<(2 * Ev + TB - 1) / TB, TB>>>(e1, e2);
    // dedup + fused rowbuild + fused pq for pair A
    k_dedup2<<<NDBLK + (Nv + TB - 1) / TB, TB>>>(g1W, g1a, g2W, g2a);

    // pair A: stage0 (list0, xp -> c1) + stage2 (list1, xp -> c4)
    k_colw2<<<(2 * Nv) / 8, 256>>>(0, 1, 0, 0, 0, g1lw, g1lb, g2lw, g2lb);
    k_gather2<<<(2 * BN * GSUB) / TB, TB>>>(0, 1, 0, 0, 1, 3, 0, 1,
                                            gcnW, gcnb, g1W, g1a, g2W, g2a);

    // pair B: stage1 (list0, c1 -> c2) + stage3 (list1, c4 -> c5)
    k_colw2<<<(2 * Nv) / 8, 256>>>(0, 1, 1, 3, 2, g1lw, g1lb, g2lw, g2lb);
    k_gather2<<<(2 * BN * GSUB) / TB, TB>>>(0, 1, 1, 3, 2, 5, 2, 0,
                                            gcnW, gcnb, g1W, g1a, g2W, g2a);

    k_lstm<<<(BN + LTB - 1) / LTB, LTB>>>(Wih0, Whh0, bih0, bhh0,
                                          Wih1, Whh1, bih1, bhh1,
                                          fc1W, fc1b, fc2W, fc2b, fc3W, fc3b,
                                          (float*)d_out, out_size);
}

// round 14
// speedup vs baseline: 2.5224x; 1.0444x over previous
#include <cuda_runtime.h>
#include <math.h>

// Problem constants
#define Bv 4
#define Nv 8192
#define Sv 12
#define Lv 5
#define Ev 131072
#define CAP 128
#define BN (Bv*Nv)        // 32768 sequences
#define FSZ (Bv*Nv*Sv)    // floats per feature map

// ---------------- scratch ----------------
__device__ float g_xpA[FSZ], g_xpB[FSZ];
__device__ float g_c1A[FSZ], g_c1B[FSZ];
__device__ float g_c2A[FSZ], g_c2B[FSZ];
__device__ float g_c4A[FSZ], g_c4B[FSZ];
__device__ float g_c5A[FSZ], g_c5B[FSZ];

// zero-initialized at module load; re-zeroed at the end of k_lstm each run
__device__ int g_fill [2][Nv];
__device__ int g_ci   [2][Nv*CAP];
__device__ int g_ucnt [2][Nv];
__device__ int g_uci  [2][Nv*CAP];
__device__ int g_mult [2][Nv*CAP];
__device__ int g_rfill[2][Nv];
__device__ int g_reid [2][Nv*CAP];

__device__ float g_p[2][Nv];          // per paired-stage slot
__device__ float g_q[2][Nv];
__device__ float g_w[2][Nv*CAP];
__device__ float g_esum[4][Bv*Sv];    // per-stage-slot rank-1 correction

__device__ __forceinline__ const float* bufA(int id) {
    switch (id) { case 0: return g_xpA; case 1: return g_c1A; case 2: return g_c2A;
                  case 3: return g_c4A; default: return g_c5A; }
}
__device__ __forceinline__ float* bufAw(int id) {
    switch (id) { case 0: return g_xpA; case 1: return g_c1A; case 2: return g_c2A;
                  case 3: return g_c4A; default: return g_c5A; }
}
__device__ __forceinline__ float* bufBw(int id) {
    switch (id) { case 0: return g_xpB; case 1: return g_c1B; case 2: return g_c2B;
                  case 3: return g_c4B; default: return g_c5B; }
}

// single-MUFU activations (sm_75+ tanh.approx)
__device__ __forceinline__ float tanh_ap(float x) {
    float y;
    asm("tanh.approx.f32 %0, %1;" : "=f"(y) : "f"(x));
    return y;
}
__device__ __forceinline__ float sigmf(float x) {
    return 0.5f * tanh_ap(0.5f * x) + 0.5f;
}

// ---------------- fused transpose + bucket ----------------
// counters (g_fill/g_rfill/g_esum) are already zero on entry:
// zero-init at load for the first call; k_lstm re-zeros at the end of each run.
#define TRB ((FSZ + 255) / 256)
#define BKB ((2 * Ev + 255) / 256)
__global__ void k_initbucket(const float* __restrict__ x,
                             const int* __restrict__ e1,
                             const int* __restrict__ e2) {
    if (blockIdx.x < TRB) {
        int idx = blockIdx.x * 256 + threadIdx.x;
        if (idx >= FSZ) return;
        int n = idx % Nv;
        int r = idx / Nv;
        int s = r % Sv;
        int b = r / Sv;
        float v = x[idx];
        g_xpA[(b * Nv + n) * Sv + s] = v;
        g_xpB[s * BN + b * Nv + n]   = v;
    } else {
        int k = (blockIdx.x - TRB) * 256 + threadIdx.x;
        if (k >= 2 * Ev) return;
        int lid = k >= Ev;
        int kk = k - lid * Ev;
        const int* ed = lid ? e2 : e1;
        int i = ed[kk];
        int j = ed[Ev + kk];
        int pos = atomicAdd(&g_fill[lid][j], 1);
        if (pos < CAP) g_ci[lid][j * CAP + pos] = i;
    }
}

// warp-per-column dedup + fused row-CSR build + fused pq for pair A
#define DWPB 8
#define NDBLK ((2 * Nv) / DWPB)
__global__ void k_dedup2(const float* __restrict__ g1W, const float* __restrict__ g1a,
                         const float* __restrict__ g2W, const float* __restrict__ g2a) {
    if (blockIdx.x >= NDBLK) {
        // ---- pq for pair A: slot0 = g1 on xp, slot1 = g2 on xp ----
        __shared__ float wa[2][Sv], wb[2][Sv];
        int t = threadIdx.x;
        if (t < Sv) {
            float s1 = 0.f, s2 = 0.f;
            #pragma unroll
            for (int u = 0; u < Sv; u++) {
                float w = g1W[t * Sv + u];
                s1 += w * g1a[u];
                s2 += w * g1a[Sv + u];
            }
            wa[0][t] = s1; wb[0][t] = s2;
        } else if (t >= 32 && t < 32 + Sv) {
            int tt = t - 32;
            float s1 = 0.f, s2 = 0.f;
            #pragma unroll
            for (int u = 0; u < Sv; u++) {
                float w = g2W[tt * Sv + u];
                s1 += w * g2a[u];
                s2 += w * g2a[Sv + u];
            }
            wa[1][tt] = s1; wb[1][tt] = s2;
        }
        __syncthreads();
        int i = (blockIdx.x - NDBLK) * blockDim.x + threadIdx.x;
        if (i >= Nv) return;
        float pA = 0.f, qA = 0.f, pB = 0.f, qB = 0.f;
        #pragma unroll
        for (int s = 0; s < Sv; s++) {
            float v = g_xpA[i * Sv + s];
            pA += v * wa[0][s]; qA += v * wb[0][s];
            pB += v * wa[1][s]; qB += v * wb[1][s];
        }
        g_p[0][i] = pA; g_q[0][i] = qA;
        g_p[1][i] = pB; g_q[1][i] = qB;
        return;
    }

    __shared__ int s_ci[DWPB][CAP];
    int warp = threadIdx.x >> 5;
    int lane = threadIdx.x & 31;
    int jj = blockIdx.x * DWPB + warp;
    int lid = jj >= Nv;
    int j = jj - lid * Nv;
    int k = min(g_fill[lid][j], CAP);
    const int* ci = g_ci[lid] + j * CAP;
    for (int t = lane; t < k; t += 32) s_ci[warp][t] = ci[t];
    __syncwarp();
    int* uci = g_uci[lid] + j * CAP;
    int* mlt = g_mult[lid] + j * CAP;
    int base = 0;
    for (int c = 0; c < k; c += 32) {
        int idx = c + lane;
        bool valid = idx < k;
        int i = valid ? s_ci[warp][idx] : -1;
        bool leader = valid;
        int mult = 0;
        if (valid) {
            for (int t = 0; t < idx; t++)
                if (s_ci[warp][t] == i) { leader = false; break; }
            if (leader)
                for (int t = idx; t < k; t++)
                    if (s_ci[warp][t] == i) mult++;
        }
        unsigned bal = __ballot_sync(0xFFFFFFFF, leader);
        if (leader) {
            int pos = base + __popc(bal & ((1u << lane) - 1));
            uci[pos] = i; mlt[pos] = mult;
            int rp = atomicAdd(&g_rfill[lid][i], 1);
            if (rp < CAP) g_reid[lid][i * CAP + rp] = j * CAP + pos;
        }
        base += __popc(bal);
    }
    if (lane == 0) g_ucnt[lid][j] = base;
}

// warp-per-column softmax; slot A uses list lidA, slot B list lidB
__global__ void k_colw2(int lidA, int lidB, int xidA, int xidB, int esumBase,
                        const float* __restrict__ lwA, const float* __restrict__ lbA,
                        const float* __restrict__ lwB, const float* __restrict__ lbB) {
    int warp = threadIdx.x >> 5;
    int lane = threadIdx.x & 31;
    int jj = blockIdx.x * (blockDim.x >> 5) + warp;
    if (jj >= 2 * Nv) return;
    int sid = jj >= Nv;
    int j = jj - sid * Nv;
    int lid = sid ? lidB : lidA;
    int u = g_ucnt[lid][j];
    if (u == 0) {
        const float* X = bufA(sid ? xidB : xidA);
        for (int t = lane; t < Bv * Sv; t += 32) {
            int b = t / Sv, s = t - b * Sv;
            atomicAdd(&g_esum[esumBase + sid][t], X[(b * Nv + j) * Sv + s]);
        }
        return;
    }
    const int* uci = g_uci[lid] + j * CAP;
    const int* mlt = g_mult[lid] + j * CAP;
    float* wv = g_w[sid] + j * CAP;
    float qj = g_q[sid][j];
    float lwv = sid ? lwB[0] : lwA[0];
    float lbv = sid ? lbB[0] : lbA[0];
    float vals[4];
    int cnt = 0;
    float m = -1e30f;
    for (int t = lane; t < u; t += 32) {
        float e = g_p[sid][uci[t]] + qj;
        e = (e > 0.f) ? e : 0.2f * e;
        float val = (float)mlt[t] * (e * lwv + lbv);
        vals[cnt++] = val;
        m = fmaxf(m, val);
    }
    #pragma unroll
    for (int o = 16; o; o >>= 1) m = fmaxf(m, __shfl_xor_sync(0xFFFFFFFF, m, o));
    float den = 0.f;
    for (int c = 0; c < cnt; c++) {
        vals[c] = __expf(vals[c] - m);
        den += vals[c];
    }
    #pragma unroll
    for (int o = 16; o; o >>= 1) den += __shfl_xor_sync(0xFFFFFFFF, den, o);
    float inv = 1.0f / den;
    cnt = 0;
    for (int t = lane; t < u; t += 32) wv[t] = vals[cnt++] * inv;
}

// gather SpMM + fused GCN; 8 threads per (slot,b,i), shuffle reduction.
#define GSUB 8
__global__ void k_gather2(int lidA, int lidB, int xidA, int xidB,
                          int outA, int outB, int esumBase, int doPQ,
                          const float* __restrict__ gcnW,
                          const float* __restrict__ gcnb,
                          const float* __restrict__ g1W, const float* __restrict__ g1a,
                          const float* __restrict__ g2W, const float* __restrict__ g2a) {
    __shared__ float sW[Sv * Sv], sb[Sv];
    __shared__ float wa[2][Sv], wb[2][Sv];
    int tx = threadIdx.x;
    if (tx < Sv * Sv) sW[tx] = gcnW[tx];
    if (tx < Sv) sb[tx] = gcnb[tx];
    if (doPQ) {
        if (tx < Sv) {
            float s1 = 0.f, s2 = 0.f;
            #pragma unroll
            for (int u = 0; u < Sv; u++) {
                float w = g1W[tx * Sv + u];
                s1 += w * g1a[u];
                s2 += w * g1a[Sv + u];
            }
            wa[0][tx] = s1; wb[0][tx] = s2;
        } else if (tx >= 32 && tx < 32 + Sv) {
            int tt = tx - 32;
            float s1 = 0.f, s2 = 0.f;
            #pragma unroll
            for (int u = 0; u < Sv; u++) {
                float w = g2W[tt * Sv + u];
                s1 += w * g2a[u];
                s2 += w * g2a[Sv + u];
            }
            wa[1][tt] = s1; wb[1][tt] = s2;
        }
    }
    __syncthreads();

    int gtid = blockIdx.x * blockDim.x + threadIdx.x;
    int gid = gtid / GSUB;      // (slot,b,i) id
    int sub = gtid % GSUB;
    if (gid >= 2 * BN) return;
    int sid = gid >= BN;
    int rem = gid - sid * BN;
    int i = rem & (Nv - 1);
    int b = rem >> 13;
    int lid = sid ? lidB : lidA;

    const float* X = bufA(sid ? xidB : xidA);
    const int* reid = g_reid[lid] + i * CAP;
    const float* wv = g_w[sid];
    int deg = min(g_rfill[lid][i], CAP);

    float z[Sv];
    #pragma unroll
    for (int s = 0; s < Sv; s++) z[s] = 0.f;

    #pragma unroll 2
    for (int t = sub; t < deg; t += GSUB) {
        int eid = reid[t];
        float w = wv[eid];
        int j = eid >> 7;   // CAP = 128
        const float4* xr = (const float4*)(X + (b * Nv + j) * Sv);
        float4 v0 = xr[0], v1 = xr[1], v2 = xr[2];
        z[0] += w * v0.x; z[1] += w * v0.y; z[2]  += w * v0.z; z[3]  += w * v0.w;
        z[4] += w * v1.x; z[5] += w * v1.y; z[6]  += w * v1.z; z[7]  += w * v1.w;
        z[8] += w * v2.x; z[9] += w * v2.y; z[10] += w * v2.z; z[11] += w * v2.w;
    }
    #pragma unroll
    for (int o = 1; o < GSUB; o <<= 1) {
        #pragma unroll
        for (int s = 0; s < Sv; s++)
            z[s] += __shfl_xor_sync(0xFFFFFFFF, z[s], o);
    }
    if (sub != 0) return;

    #pragma unroll
    for (int s = 0; s < Sv; s++)
        z[s] += g_esum[esumBase + sid][b * Sv + s] * (1.0f / (float)Nv);

    float* OA = bufAw(sid ? outB : outA);
    float* OB = bufBw(sid ? outB : outA);
    int tid = b * Nv + i;
    float yv[Sv];
    float pN = 0.f, qN = 0.f;
    #pragma unroll
    for (int s = 0; s < Sv; s++) {
        float y = sb[s];
        #pragma unroll
        for (int t = 0; t < Sv; t++) y += z[t] * sW[s * Sv + t];
        y = (y > 0.f) ? y : 0.01f * y;
        yv[s] = y;
        OB[s * BN + tid] = y;
        pN += y * wa[sid][s];
        qN += y * wb[sid][s];
    }
    // vectorized A-layout store (rows are 16B-aligned: tid*48 bytes)
    float4* oa4 = (float4*)(OA + tid * Sv);
    oa4[0] = make_float4(yv[0], yv[1], yv[2],  yv[3]);
    oa4[1] = make_float4(yv[4], yv[5], yv[6],  yv[7]);
    oa4[2] = make_float4(yv[8], yv[9], yv[10], yv[11]);

    if (doPQ && b == 0) {
        g_p[sid][i] = pN;
        g_q[sid][i] = qN;
    }
}

// ---------------- fused 2-layer LSTM + TPA head ----------------
// v3: h history in shared; weights repacked float4+remainder (halves LDS count);
// tail re-zeros the graph-state counters for the next replay.
#define LTB 128
__global__ void __launch_bounds__(LTB)
k_lstm(const float* __restrict__ Wih0, const float* __restrict__ Whh0,
       const float* __restrict__ bih0, const float* __restrict__ bhh0,
       const float* __restrict__ Wih1, const float* __restrict__ Whh1,
       const float* __restrict__ bih1, const float* __restrict__ bhh1,
       const float* __restrict__ fc1W, const float* __restrict__ fc1b,
       const float* __restrict__ fc2W, const float* __restrict__ fc2b,
       const float* __restrict__ fc3W, const float* __restrict__ fc3b,
       float* __restrict__ out, int out_size) {
    __shared__ float4 sWi0[20], sWh0[20], sWi1[20], sWh1[20];
    __shared__ float  sWi0r[20], sWh0r[20], sWi1r[20], sWh1r[20];
    __shared__ float  sB0[20], sB1[20];
    __shared__ float  sF1[176], sF1b[16], sF2[80], sF2b[5], sF3[21], sF3b;
    __shared__ float  sH[(Sv - 1) * Lv * LTB];   // h1 per timestep (0..10), per thread
    int t = threadIdx.x;
    for (int i = t; i < 20; i += blockDim.x) {
        sWi0[i] = make_float4(Wih0[i*5+0], Wih0[i*5+1], Wih0[i*5+2], Wih0[i*5+3]);
        sWi0r[i] = Wih0[i*5+4];
        sWh0[i] = make_float4(Whh0[i*5+0], Whh0[i*5+1], Whh0[i*5+2], Whh0[i*5+3]);
        sWh0r[i] = Whh0[i*5+4];
        sWi1[i] = make_float4(Wih1[i*5+0], Wih1[i*5+1], Wih1[i*5+2], Wih1[i*5+3]);
        sWi1r[i] = Wih1[i*5+4];
        sWh1[i] = make_float4(Whh1[i*5+0], Whh1[i*5+1], Whh1[i*5+2], Whh1[i*5+3]);
        sWh1r[i] = Whh1[i*5+4];
        sB0[i] = bih0[i] + bhh0[i];
        sB1[i] = bih1[i] + bhh1[i];
    }
    for (int i = t; i < 176; i += blockDim.x) sF1[i] = fc1W[i];
    for (int i = t; i < 80;  i += blockDim.x) sF2[i] = fc2W[i];
    for (int i = t; i < 21;  i += blockDim.x) sF3[i] = fc3W[i];
    for (int i = t; i < 16;  i += blockDim.x) sF1b[i] = fc1b[i];
    for (int i = t; i < 5;   i += blockDim.x) sF2b[i] = fc2b[i];
    if (t == 0) sF3b = fc3b[0];
    __syncthreads();

    int seq = blockIdx.x * blockDim.x + threadIdx.x;
    if (seq < BN) {
        float h0[Lv], c0[Lv], h1[Lv], c1l[Lv];
        #pragma unroll
        for (int l = 0; l < Lv; l++) { h0[l]=0.f; c0[l]=0.f; h1[l]=0.f; c1l[l]=0.f; }

        #pragma unroll 1
        for (int tt = 0; tt < Sv; tt++) {
            float xv[Lv];
            xv[0] = g_xpB[tt * BN + seq];
            xv[1] = g_c1B[tt * BN + seq];
            xv[2] = g_c2B[tt * BN + seq];
            xv[3] = g_c4B[tt * BN + seq];
            xv[4] = g_c5B[tt * BN + seq];

            float z[20];
            #pragma unroll
            for (int g = 0; g < 20; g++) {
                float4 wi = sWi0[g], wh = sWh0[g];
                z[g] = sB0[g]
                     + wi.x*xv[0] + wi.y*xv[1] + wi.z*xv[2] + wi.w*xv[3] + sWi0r[g]*xv[4]
                     + wh.x*h0[0] + wh.y*h0[1] + wh.z*h0[2] + wh.w*h0[3] + sWh0r[g]*h0[4];
            }
            #pragma unroll
            for (int l = 0; l < Lv; l++) {
                float ig = sigmf(z[l]);
                float fg = sigmf(z[5 + l]);
                float gg = tanh_ap(z[10 + l]);
                float og = sigmf(z[15 + l]);
                c0[l] = fg * c0[l] + ig * gg;
                h0[l] = og * tanh_ap(c0[l]);
            }
            #pragma unroll
            for (int g = 0; g < 20; g++) {
                float4 wi = sWi1[g], wh = sWh1[g];
                z[g] = sB1[g]
                     + wi.x*h0[0] + wi.y*h0[1] + wi.z*h0[2] + wi.w*h0[3] + sWi1r[g]*h0[4]
                     + wh.x*h1[0] + wh.y*h1[1] + wh.z*h1[2] + wh.w*h1[3] + sWh1r[g]*h1[4];
            }
            #pragma unroll
            for (int l = 0; l < Lv; l++) {
                float ig = sigmf(z[l]);
                float fg = sigmf(z[5 + l]);
                float gg = tanh_ap(z[10 + l]);
                float og = sigmf(z[15 + l]);
                c1l[l] = fg * c1l[l] + ig * gg;
                h1[l] = og * tanh_ap(c1l[l]);
            }
            if (tt < Sv - 1) {
                #pragma unroll
                for (int l = 0; l < Lv; l++)
                    sH[(tt * Lv + l) * LTB + t] = h1[l];
            }
        }

        float ht[Lv];
        #pragma unroll
        for (int m = 0; m < Lv; m++) ht[m] = h1[m];

        float Hc[Lv][16];
        #pragma unroll
        for (int l = 0; l < Lv; l++) {
            #pragma unroll
            for (int k = 0; k < 16; k++) Hc[l][k] = sF1b[k];
            #pragma unroll
            for (int tt = 0; tt < Sv - 1; tt++) {
                float hv = sH[(tt * Lv + l) * LTB + t];
                #pragma unroll
                for (int k = 0; k < 16; k++)
                    Hc[l][k] += hv * sF1[k * (Sv - 1) + tt];
            }
        }

        float av[Lv];
        #pragma unroll
        for (int l = 0; l < Lv; l++) {
            float s = 0.f;
            #pragma unroll
            for (int m = 0; m < Lv; m++) {
                float hn = sF2b[m];
                #pragma unroll
                for (int k = 0; k < 16; k++) hn += Hc[l][k] * sF2[m * 16 + k];
                s += hn * ht[m];
            }
            av[l] = sigmf(s);
        }

        float y = sF3b;
        #pragma unroll
        for (int k = 0; k < 16; k++) {
            float vt = 0.f;
            #pragma unroll
            for (int l = 0; l < Lv; l++) vt += av[l] * Hc[l][k];
            y += vt * sF3[k];
        }
        #pragma unroll
        for (int m = 0; m < Lv; m++) y += ht[m] * sF3[16 + m];

        out[seq] = y;
        if (BN + seq * Lv + (Lv - 1) < out_size) {
            #pragma unroll
            for (int l = 0; l < Lv; l++)
                out[BN + seq * Lv + l] = av[l];
        }
    }

    // re-zero graph-state counters for the next replay
    int idx = blockIdx.x * blockDim.x + threadIdx.x;
    if (idx < Nv) {
        g_fill[0][idx] = 0; g_fill[1][idx] = 0;
        g_rfill[0][idx] = 0; g_rfill[1][idx] = 0;
    }
    if (idx < 4 * Bv * Sv) ((float*)g_esum)[idx] = 0.0f;
}

// ---------------- launcher ----------------
extern "C" void kernel_launch(void* const* d_in, const int* in_sizes, int n_in,
                              void* d_out, int out_size) {
    const float* x    = (const float*)d_in[0];
    const int*   e1   = (const int*)  d_in[1];
    const int*   e2   = (const int*)  d_in[2];
    const float* g1W  = (const float*)d_in[3];
    const float* g1a  = (const float*)d_in[4];
    const float* g1lw = (const float*)d_in[5];
    const float* g1lb = (const float*)d_in[6];
    const float* g2W  = (const float*)d_in[7];
    const float* g2a  = (const float*)d_in[8];
    const float* g2lw = (const float*)d_in[9];
    const float* g2lb = (const float*)d_in[10];
    const float* gcnW = (const float*)d_in[11];
    const float* gcnb = (const float*)d_in[12];
    const float* Wih0 = (const float*)d_in[13];
    const float* Whh0 = (const float*)d_in[14];
    const float* bih0 = (const float*)d_in[15];
    const float* bhh0 = (const float*)d_in[16];
    const float* Wih1 = (const float*)d_in[17];
    const float* Whh1 = (const float*)d_in[18];
    const float* bih1 = (const float*)d_in[19];
    const float* bhh1 = (const float*)d_in[20];
    const float* fc1W = (const float*)d_in[21];
    const float* fc1b = (const float*)d_in[22];
    const float* fc2W = (const float*)d_in[23];
    const float* fc2b = (const float*)d_in[24];
    const float* fc3W = (const float*)d_in[25];
    const float* fc3b = (const float*)d_in[26];

    const int TB = 256;
    // launch 0: fused transpose + bucket (counters pre-zeroed by prior lstm / load-init)
    k_initbucket<<<TRB + BKB, 256>>>(x, e1, e2);
    // launch 1: dedup + fused rowbuild + fused pq for pair A
    k_dedup2<<<NDBLK + (Nv + TB - 1) / TB, TB>>>(g1W, g1a, g2W, g2a);

    // pair A: stage0 (list0, xp -> c1) + stage2 (list1, xp -> c4)
    k_colw2<<<(2 * Nv) / 8, 256>>>(0, 1, 0, 0, 0, g1lw, g1lb, g2lw, g2lb);
    k_gather2<<<(2 * BN * GSUB) / TB, TB>>>(0, 1, 0, 0, 1, 3, 0, 1,
                                            gcnW, gcnb, g1W, g1a, g2W, g2a);

    // pair B: stage1 (list0, c1 -> c2) + stage3 (list1, c4 -> c5)
    k_colw2<<<(2 * Nv) / 8, 256>>>(0, 1, 1, 3, 2, g1lw, g1lb, g2lw, g2lb);
    k_gather2<<<(2 * BN * GSUB) / TB, TB>>>(0, 1, 1, 3, 2, 5, 2, 0,
                                            gcnW, gcnb, g1W, g1a, g2W, g2a);

    k_lstm<<<(BN + LTB - 1) / LTB, LTB>>>(Wih0, Whh0, bih0, bhh0,
                                          Wih1, Whh1, bih1, bhh1,
                                          fc1W, fc1b, fc2W, fc2b, fc3W, fc3b,
                                          (float*)d_out, out_size);
}

// round 15
// speedup vs baseline: 2.8021x; 1.1109x over previous
#include <cuda_runtime.h>
#include <math.h>

// Problem constants
#define Bv 4
#define Nv 8192
#define Sv 12
#define Lv 5
#define Ev 131072
#define CAP 128
#define BN (Bv*Nv)        // 32768 sequences
#define FSZ (Bv*Nv*Sv)    // floats per feature map

// ---------------- scratch ----------------
__device__ float g_xpA[FSZ], g_xpB[FSZ];
__device__ float g_c1A[FSZ], g_c1B[FSZ];
__device__ float g_c2A[FSZ], g_c2B[FSZ];
__device__ float g_c4A[FSZ], g_c4B[FSZ];
__device__ float g_c5A[FSZ], g_c5B[FSZ];

// zero-initialized at module load; re-zeroed at the end of k_lstm each run
__device__ int g_fill [2][Nv];
__device__ int g_ci   [2][Nv*CAP];
__device__ int g_ucnt [2][Nv];
__device__ int g_uci  [2][Nv*CAP];
__device__ int g_mult [2][Nv*CAP];
__device__ int g_rfill[2][Nv];
__device__ int g_reid [2][Nv*CAP];

__device__ float g_p[2][Nv];          // per paired-stage slot
__device__ float g_q[2][Nv];
__device__ float g_w[2][Nv*CAP];
__device__ float g_esum[4][Bv*Sv];    // per-stage-slot rank-1 correction

__device__ __forceinline__ const float* bufA(int id) {
    switch (id) { case 0: return g_xpA; case 1: return g_c1A; case 2: return g_c2A;
                  case 3: return g_c4A; default: return g_c5A; }
}
__device__ __forceinline__ float* bufAw(int id) {
    switch (id) { case 0: return g_xpA; case 1: return g_c1A; case 2: return g_c2A;
                  case 3: return g_c4A; default: return g_c5A; }
}
__device__ __forceinline__ float* bufBw(int id) {
    switch (id) { case 0: return g_xpB; case 1: return g_c1B; case 2: return g_c2B;
                  case 3: return g_c4B; default: return g_c5B; }
}

// single-MUFU activations (sm_75+ tanh.approx)
__device__ __forceinline__ float tanh_ap(float x) {
    float y;
    asm("tanh.approx.f32 %0, %1;" : "=f"(y) : "f"(x));
    return y;
}
__device__ __forceinline__ float sigmf(float x) {
    return 0.5f * tanh_ap(0.5f * x) + 0.5f;
}

// ---------------- fused transpose + bucket ----------------
#define TRB ((FSZ + 255) / 256)
#define BKB ((2 * Ev + 255) / 256)
__global__ void k_initbucket(const float* __restrict__ x,
                             const int* __restrict__ e1,
                             const int* __restrict__ e2) {
    if (blockIdx.x < TRB) {
        int idx = blockIdx.x * 256 + threadIdx.x;
        if (idx >= FSZ) return;
        int n = idx % Nv;
        int r = idx / Nv;
        int s = r % Sv;
        int b = r / Sv;
        float v = x[idx];
        g_xpA[(b * Nv + n) * Sv + s] = v;
        g_xpB[s * BN + b * Nv + n]   = v;
    } else {
        int k = (blockIdx.x - TRB) * 256 + threadIdx.x;
        if (k >= 2 * Ev) return;
        int lid = k >= Ev;
        int kk = k - lid * Ev;
        const int* ed = lid ? e2 : e1;
        int i = ed[kk];
        int j = ed[Ev + kk];
        int pos = atomicAdd(&g_fill[lid][j], 1);
        if (pos < CAP) g_ci[lid][j * CAP + pos] = i;
    }
}

// warp-per-column dedup + fused row-CSR build + fused pq for pair A
#define DWPB 8
#define NDBLK ((2 * Nv) / DWPB)
__global__ void k_dedup2(const float* __restrict__ g1W, const float* __restrict__ g1a,
                         const float* __restrict__ g2W, const float* __restrict__ g2a) {
    if (blockIdx.x >= NDBLK) {
        __shared__ float wa[2][Sv], wb[2][Sv];
        int t = threadIdx.x;
        if (t < Sv) {
            float s1 = 0.f, s2 = 0.f;
            #pragma unroll
            for (int u = 0; u < Sv; u++) {
                float w = g1W[t * Sv + u];
                s1 += w * g1a[u];
                s2 += w * g1a[Sv + u];
            }
            wa[0][t] = s1; wb[0][t] = s2;
        } else if (t >= 32 && t < 32 + Sv) {
            int tt = t - 32;
            float s1 = 0.f, s2 = 0.f;
            #pragma unroll
            for (int u = 0; u < Sv; u++) {
                float w = g2W[tt * Sv + u];
                s1 += w * g2a[u];
                s2 += w * g2a[Sv + u];
            }
            wa[1][tt] = s1; wb[1][tt] = s2;
        }
        __syncthreads();
        int i = (blockIdx.x - NDBLK) * blockDim.x + threadIdx.x;
        if (i >= Nv) return;
        float pA = 0.f, qA = 0.f, pB = 0.f, qB = 0.f;
        #pragma unroll
        for (int s = 0; s < Sv; s++) {
            float v = g_xpA[i * Sv + s];
            pA += v * wa[0][s]; qA += v * wb[0][s];
            pB += v * wa[1][s]; qB += v * wb[1][s];
        }
        g_p[0][i] = pA; g_q[0][i] = qA;
        g_p[1][i] = pB; g_q[1][i] = qB;
        return;
    }

    __shared__ int s_ci[DWPB][CAP];
    int warp = threadIdx.x >> 5;
    int lane = threadIdx.x & 31;
    int jj = blockIdx.x * DWPB + warp;
    int lid = jj >= Nv;
    int j = jj - lid * Nv;
    int k = min(g_fill[lid][j], CAP);
    const int* ci = g_ci[lid] + j * CAP;
    for (int t = lane; t < k; t += 32) s_ci[warp][t] = ci[t];
    __syncwarp();
    int* uci = g_uci[lid] + j * CAP;
    int* mlt = g_mult[lid] + j * CAP;
    int base = 0;
    for (int c = 0; c < k; c += 32) {
        int idx = c + lane;
        bool valid = idx < k;
        int i = valid ? s_ci[warp][idx] : -1;
        bool leader = valid;
        int mult = 0;
        if (valid) {
            for (int t = 0; t < idx; t++)
                if (s_ci[warp][t] == i) { leader = false; break; }
            if (leader)
                for (int t = idx; t < k; t++)
                    if (s_ci[warp][t] == i) mult++;
        }
        unsigned bal = __ballot_sync(0xFFFFFFFF, leader);
        if (leader) {
            int pos = base + __popc(bal & ((1u << lane) - 1));
            uci[pos] = i; mlt[pos] = mult;
            int rp = atomicAdd(&g_rfill[lid][i], 1);
            if (rp < CAP) g_reid[lid][i * CAP + rp] = j * CAP + pos;
        }
        base += __popc(bal);
    }
    if (lane == 0) g_ucnt[lid][j] = base;
}

// warp-per-column softmax; slot A uses list lidA, slot B list lidB
__global__ void k_colw2(int lidA, int lidB, int xidA, int xidB, int esumBase,
                        const float* __restrict__ lwA, const float* __restrict__ lbA,
                        const float* __restrict__ lwB, const float* __restrict__ lbB) {
    int warp = threadIdx.x >> 5;
    int lane = threadIdx.x & 31;
    int jj = blockIdx.x * (blockDim.x >> 5) + warp;
    if (jj >= 2 * Nv) return;
    int sid = jj >= Nv;
    int j = jj - sid * Nv;
    int lid = sid ? lidB : lidA;
    int u = g_ucnt[lid][j];
    if (u == 0) {
        const float* X = bufA(sid ? xidB : xidA);
        for (int t = lane; t < Bv * Sv; t += 32) {
            int b = t / Sv, s = t - b * Sv;
            atomicAdd(&g_esum[esumBase + sid][t], X[(b * Nv + j) * Sv + s]);
        }
        return;
    }
    const int* uci = g_uci[lid] + j * CAP;
    const int* mlt = g_mult[lid] + j * CAP;
    float* wv = g_w[sid] + j * CAP;
    float qj = g_q[sid][j];
    float lwv = sid ? lwB[0] : lwA[0];
    float lbv = sid ? lbB[0] : lbA[0];
    float vals[4];
    int cnt = 0;
    float m = -1e30f;
    for (int t = lane; t < u; t += 32) {
        float e = g_p[sid][uci[t]] + qj;
        e = (e > 0.f) ? e : 0.2f * e;
        float val = (float)mlt[t] * (e * lwv + lbv);
        vals[cnt++] = val;
        m = fmaxf(m, val);
    }
    #pragma unroll
    for (int o = 16; o; o >>= 1) m = fmaxf(m, __shfl_xor_sync(0xFFFFFFFF, m, o));
    float den = 0.f;
    for (int c = 0; c < cnt; c++) {
        vals[c] = __expf(vals[c] - m);
        den += vals[c];
    }
    #pragma unroll
    for (int o = 16; o; o >>= 1) den += __shfl_xor_sync(0xFFFFFFFF, den, o);
    float inv = 1.0f / den;
    cnt = 0;
    for (int t = lane; t < u; t += 32) wv[t] = vals[cnt++] * inv;
}

// gather SpMM + fused GCN; 4 lanes cooperate on ONE (slot,b,i) row.
// lanes 0-2 each load one float4 of the neighbor row (same 128B line ->
// coalesced); each lane owns an s-quarter and computes a partial GCN;
// 2-step shfl_xor reduces the 12 outputs.
#define GSUB 4
__global__ void k_gather2(int lidA, int lidB, int xidA, int xidB,
                          int outA, int outB, int esumBase, int doPQ,
                          const float* __restrict__ gcnW,
                          const float* __restrict__ gcnb,
                          const float* __restrict__ g1W, const float* __restrict__ g1a,
                          const float* __restrict__ g2W, const float* __restrict__ g2a) {
    __shared__ float sW[Sv * Sv], sb[Sv];
    __shared__ float wa[2][Sv], wb[2][Sv];
    int tx = threadIdx.x;
    if (tx < Sv * Sv) sW[tx] = gcnW[tx];
    if (tx < Sv) sb[tx] = gcnb[tx];
    if (doPQ) {
        if (tx < Sv) {
            float s1 = 0.f, s2 = 0.f;
            #pragma unroll
            for (int u = 0; u < Sv; u++) {
                float w = g1W[tx * Sv + u];
                s1 += w * g1a[u];
                s2 += w * g1a[Sv + u];
            }
            wa[0][tx] = s1; wb[0][tx] = s2;
        } else if (tx >= 32 && tx < 32 + Sv) {
            int tt = tx - 32;
            float s1 = 0.f, s2 = 0.f;
            #pragma unroll
            for (int u = 0; u < Sv; u++) {
                float w = g2W[tt * Sv + u];
                s1 += w * g2a[u];
                s2 += w * g2a[Sv + u];
            }
            wa[1][tt] = s1; wb[1][tt] = s2;
        }
    }
    __syncthreads();

    int gtid = blockIdx.x * blockDim.x + threadIdx.x;
    int gid = gtid >> 2;        // (slot,b,i) id
    int sub = gtid & 3;
    if (gid >= 2 * BN) return;
    int sid = gid >= BN;
    int rem = gid - sid * BN;
    int i = rem & (Nv - 1);
    int b = rem >> 13;
    int lid = sid ? lidB : lidA;

    const float* X = bufA(sid ? xidB : xidA);
    const int* reid = g_reid[lid] + i * CAP;
    const float* wv = g_w[sid];
    int deg = min(g_rfill[lid][i], CAP);
    bool lively = sub < 3;

    float4 zq = make_float4(0.f, 0.f, 0.f, 0.f);
    #pragma unroll 4
    for (int t = 0; t < deg; t++) {
        int eid = reid[t];          // broadcast (same addr across group)
        float w = wv[eid];          // broadcast
        int j = eid >> 7;           // CAP = 128
        if (lively) {
            float4 v = ((const float4*)(X + (b * Nv + j) * Sv))[sub];
            zq.x += w * v.x; zq.y += w * v.y; zq.z += w * v.z; zq.w += w * v.w;
        }
    }
    if (lively) {
        const float* es = g_esum[esumBase + sid] + b * Sv + sub * 4;
        zq.x += es[0] * (1.0f / (float)Nv);
        zq.y += es[1] * (1.0f / (float)Nv);
        zq.z += es[2] * (1.0f / (float)Nv);
        zq.w += es[3] * (1.0f / (float)Nv);
    }

    // partial GCN: each lane's quarter against its sW columns
    float ps[Sv];
    #pragma unroll
    for (int s = 0; s < Sv; s++) {
        float acc = 0.f;
        if (lively) {
            const float* wr = sW + s * Sv + sub * 4;
            acc = zq.x * wr[0] + zq.y * wr[1] + zq.z * wr[2] + zq.w * wr[3];
        }
        ps[s] = acc;
    }
    #pragma unroll
    for (int o = 1; o < 4; o <<= 1) {
        #pragma unroll
        for (int s = 0; s < Sv; s++)
            ps[s] += __shfl_xor_sync(0xFFFFFFFF, ps[s], o);
    }
    if (sub != 0) return;

    float* OA = bufAw(sid ? outB : outA);
    float* OB = bufBw(sid ? outB : outA);
    int tid = b * Nv + i;
    float yv[Sv];
    float pN = 0.f, qN = 0.f;
    #pragma unroll
    for (int s = 0; s < Sv; s++) {
        float y = ps[s] + sb[s];
        y = (y > 0.f) ? y : 0.01f * y;
        yv[s] = y;
        OB[s * BN + tid] = y;
        pN += y * wa[sid][s];
        qN += y * wb[sid][s];
    }
    float4* oa4 = (float4*)(OA + tid * Sv);
    oa4[0] = make_float4(yv[0], yv[1], yv[2],  yv[3]);
    oa4[1] = make_float4(yv[4], yv[5], yv[6],  yv[7]);
    oa4[2] = make_float4(yv[8], yv[9], yv[10], yv[11]);

    if (doPQ && b == 0) {
        g_p[sid][i] = pN;
        g_q[sid][i] = qN;
    }
}

// ---------------- fused 2-layer LSTM + TPA head ----------------
#define LTB 128
__global__ void __launch_bounds__(LTB)
k_lstm(const float* __restrict__ Wih0, const float* __restrict__ Whh0,
       const float* __restrict__ bih0, const float* __restrict__ bhh0,
       const float* __restrict__ Wih1, const float* __restrict__ Whh1,
       const float* __restrict__ bih1, const float* __restrict__ bhh1,
       const float* __restrict__ fc1W, const float* __restrict__ fc1b,
       const float* __restrict__ fc2W, const float* __restrict__ fc2b,
       const float* __restrict__ fc3W, const float* __restrict__ fc3b,
       float* __restrict__ out, int out_size) {
    __shared__ float4 sWi0[20], sWh0[20], sWi1[20], sWh1[20];
    __shared__ float  sWi0r[20], sWh0r[20], sWi1r[20], sWh1r[20];
    __shared__ float  sB0[20], sB1[20];
    __shared__ float  sF1[176], sF1b[16], sF2[80], sF2b[5], sF3[21], sF3b;
    __shared__ float  sH[(Sv - 1) * Lv * LTB];
    int t = threadIdx.x;
    for (int i = t; i < 20; i += blockDim.x) {
        sWi0[i] = make_float4(Wih0[i*5+0], Wih0[i*5+1], Wih0[i*5+2], Wih0[i*5+3]);
        sWi0r[i] = Wih0[i*5+4];
        sWh0[i] = make_float4(Whh0[i*5+0], Whh0[i*5+1], Whh0[i*5+2], Whh0[i*5+3]);
        sWh0r[i] = Whh0[i*5+4];
        sWi1[i] = make_float4(Wih1[i*5+0], Wih1[i*5+1], Wih1[i*5+2], Wih1[i*5+3]);
        sWi1r[i] = Wih1[i*5+4];
        sWh1[i] = make_float4(Whh1[i*5+0], Whh1[i*5+1], Whh1[i*5+2], Whh1[i*5+3]);
        sWh1r[i] = Whh1[i*5+4];
        sB0[i] = bih0[i] + bhh0[i];
        sB1[i] = bih1[i] + bhh1[i];
    }
    for (int i = t; i < 176; i += blockDim.x) sF1[i] = fc1W[i];
    for (int i = t; i < 80;  i += blockDim.x) sF2[i] = fc2W[i];
    for (int i = t; i < 21;  i += blockDim.x) sF3[i] = fc3W[i];
    for (int i = t; i < 16;  i += blockDim.x) sF1b[i] = fc1b[i];
    for (int i = t; i < 5;   i += blockDim.x) sF2b[i] = fc2b[i];
    if (t == 0) sF3b = fc3b[0];
    __syncthreads();

    int seq = blockIdx.x * blockDim.x + threadIdx.x;
    if (seq < BN) {
        float h0[Lv], c0[Lv], h1[Lv], c1l[Lv];
        #pragma unroll
        for (int l = 0; l < Lv; l++) { h0[l]=0.f; c0[l]=0.f; h1[l]=0.f; c1l[l]=0.f; }

        #pragma unroll 1
        for (int tt = 0; tt < Sv; tt++) {
            float xv[Lv];
            xv[0] = g_xpB[tt * BN + seq];
            xv[1] = g_c1B[tt * BN + seq];
            xv[2] = g_c2B[tt * BN + seq];
            xv[3] = g_c4B[tt * BN + seq];
            xv[4] = g_c5B[tt * BN + seq];

            float z[20];
            #pragma unroll
            for (int g = 0; g < 20; g++) {
                float4 wi = sWi0[g], wh = sWh0[g];
                z[g] = sB0[g]
                     + wi.x*xv[0] + wi.y*xv[1] + wi.z*xv[2] + wi.w*xv[3] + sWi0r[g]*xv[4]
                     + wh.x*h0[0] + wh.y*h0[1] + wh.z*h0[2] + wh.w*h0[3] + sWh0r[g]*h0[4];
            }
            #pragma unroll
            for (int l = 0; l < Lv; l++) {
                float ig = sigmf(z[l]);
                float fg = sigmf(z[5 + l]);
                float gg = tanh_ap(z[10 + l]);
                float og = sigmf(z[15 + l]);
                c0[l] = fg * c0[l] + ig * gg;
                h0[l] = og * tanh_ap(c0[l]);
            }
            #pragma unroll
            for (int g = 0; g < 20; g++) {
                float4 wi = sWi1[g], wh = sWh1[g];
                z[g] = sB1[g]
                     + wi.x*h0[0] + wi.y*h0[1] + wi.z*h0[2] + wi.w*h0[3] + sWi1r[g]*h0[4]
                     + wh.x*h1[0] + wh.y*h1[1] + wh.z*h1[2] + wh.w*h1[3] + sWh1r[g]*h1[4];
            }
            #pragma unroll
            for (int l = 0; l < Lv; l++) {
                float ig = sigmf(z[l]);
                float fg = sigmf(z[5 + l]);
                float gg = tanh_ap(z[10 + l]);
                float og = sigmf(z[15 + l]);
                c1l[l] = fg * c1l[l] + ig * gg;
                h1[l] = og * tanh_ap(c1l[l]);
            }
            if (tt < Sv - 1) {
                #pragma unroll
                for (int l = 0; l < Lv; l++)
                    sH[(tt * Lv + l) * LTB + t] = h1[l];
            }
        }

        float ht[Lv];
        #pragma unroll
        for (int m = 0; m < Lv; m++) ht[m] = h1[m];

        float Hc[Lv][16];
        #pragma unroll
        for (int l = 0; l < Lv; l++) {
            #pragma unroll
            for (int k = 0; k < 16; k++) Hc[l][k] = sF1b[k];
            #pragma unroll
            for (int tt = 0; tt < Sv - 1; tt++) {
                float hv = sH[(tt * Lv + l) * LTB + t];
                #pragma unroll
                for (int k = 0; k < 16; k++)
                    Hc[l][k] += hv * sF1[k * (Sv - 1) + tt];
            }
        }

        float av[Lv];
        #pragma unroll
        for (int l = 0; l < Lv; l++) {
            float s = 0.f;
            #pragma unroll
            for (int m = 0; m < Lv; m++) {
                float hn = sF2b[m];
                #pragma unroll
                for (int k = 0; k < 16; k++) hn += Hc[l][k] * sF2[m * 16 + k];
                s += hn * ht[m];
            }
            av[l] = sigmf(s);
        }

        float y = sF3b;
        #pragma unroll
        for (int k = 0; k < 16; k++) {
            float vt = 0.f;
            #pragma unroll
            for (int l = 0; l < Lv; l++) vt += av[l] * Hc[l][k];
            y += vt * sF3[k];
        }
        #pragma unroll
        for (int m = 0; m < Lv; m++) y += ht[m] * sF3[16 + m];

        out[seq] = y;
        if (BN + seq * Lv + (Lv - 1) < out_size) {
            #pragma unroll
            for (int l = 0; l < Lv; l++)
                out[BN + seq * Lv + l] = av[l];
        }
    }

    // re-zero graph-state counters for the next replay
    int idx = blockIdx.x * blockDim.x + threadIdx.x;
    if (idx < Nv) {
        g_fill[0][idx] = 0; g_fill[1][idx] = 0;
        g_rfill[0][idx] = 0; g_rfill[1][idx] = 0;
    }
    if (idx < 4 * Bv * Sv) ((float*)g_esum)[idx] = 0.0f;
}

// ---------------- launcher ----------------
extern "C" void kernel_launch(void* const* d_in, const int* in_sizes, int n_in,
                              void* d_out, int out_size) {
    const float* x    = (const float*)d_in[0];
    const int*   e1   = (const int*)  d_in[1];
    const int*   e2   = (const int*)  d_in[2];
    const float* g1W  = (const float*)d_in[3];
    const float* g1a  = (const float*)d_in[4];
    const float* g1lw = (const float*)d_in[5];
    const float* g1lb = (const float*)d_in[6];
    const float* g2W  = (const float*)d_in[7];
    const float* g2a  = (const float*)d_in[8];
    const float* g2lw = (const float*)d_in[9];
    const float* g2lb = (const float*)d_in[10];
    const float* gcnW = (const float*)d_in[11];
    const float* gcnb = (const float*)d_in[12];
    const float* Wih0 = (const float*)d_in[13];
    const float* Whh0 = (const float*)d_in[14];
    const float* bih0 = (const float*)d_in[15];
    const float* bhh0 = (const float*)d_in[16];
    const float* Wih1 = (const float*)d_in[17];
    const float* Whh1 = (const float*)d_in[18];
    const float* bih1 = (const float*)d_in[19];
    const float* bhh1 = (const float*)d_in[20];
    const float* fc1W = (const float*)d_in[21];
    const float* fc1b = (const float*)d_in[22];
    const float* fc2W = (const float*)d_in[23];
    const float* fc2b = (const float*)d_in[24];
    const float* fc3W = (const float*)d_in[25];
    const float* fc3b = (const float*)d_in[26];

    const int TB = 256;
    // launch 0: fused transpose + bucket
    k_initbucket<<<TRB + BKB, 256>>>(x, e1, e2);
    // launch 1: dedup + fused rowbuild + fused pq for pair A
    k_dedup2<<<NDBLK + (Nv + TB - 1) / TB, TB>>>(g1W, g1a, g2W, g2a);

    // pair A: stage0 (list0, xp -> c1) + stage2 (list1, xp -> c4)
    k_colw2<<<(2 * Nv) / 8, 256>>>(0, 1, 0, 0, 0, g1lw, g1lb, g2lw, g2lb);
    k_gather2<<<(2 * BN * GSUB) / TB, TB>>>(0, 1, 0, 0, 1, 3, 0, 1,
                                            gcnW, gcnb, g1W, g1a, g2W, g2a);

    // pair B: stage1 (list0, c1 -> c2) + stage3 (list1, c4 -> c5)
    k_colw2<<<(2 * Nv) / 8, 256>>>(0, 1, 1, 3, 2, g1lw, g1lb, g2lw, g2lb);
    k_gather2<<<(2 * BN * GSUB) / TB, TB>>>(0, 1, 1, 3, 2, 5, 2, 0,
                                            gcnW, gcnb, g1W, g1a, g2W, g2a);

    k_lstm<<<(BN + LTB - 1) / LTB, LTB>>>(Wih0, Whh0, bih0, bhh0,
                                          Wih1, Whh1, bih1, bhh1,
                                          fc1W, fc1b, fc2W, fc2b, fc3W, fc3b,
                                          (float*)d_out, out_size);
}